// round 10
// baseline (speedup 1.0000x reference)
#include <cuda_runtime.h>
#include <cuda_fp16.h>
#include <math.h>
#include <stdint.h>

#define N_NODES 4096
#define N_EDGES 32768
#define DIM 64
#define EHID 128
#define NUM_STEPS 3

// ---------------- scratch (device globals; zero-initialized) ----------------
__device__ float g_h[N_NODES * DIM];
__device__ float g_e[N_EDGES * EHID];
__device__ float g_agg[N_NODES * DIM];    // invariant: zero at kernel_launch entry
__device__ __half g_h1[N_NODES * DIM];
__device__ __half g_h2[N_NODES * DIM];
__device__ __half g_e1[N_EDGES * EHID];
__device__ __half g_e2[N_EDGES * EHID];
__device__ __half g_Wt1[4096 * 128];      // W_nn^T [n][k] limb1
__device__ __half g_We1T1[128 * 256];
__device__ __half g_We1T2[128 * 256];
__device__ __half g_We2T1[128 * 128];
__device__ __half g_We2T2[128 * 128];

// ---------------- helpers ---------------------------------------------------
__device__ __forceinline__ uint32_t smem_u32(const void* p) {
    uint32_t a;
    asm("{ .reg .u64 t; cvta.to.shared.u64 t, %1; cvt.u32.u64 %0, t; }"
        : "=r"(a) : "l"(p));
    return a;
}
#define LDSM4(r, addr) \
    asm volatile("ldmatrix.sync.aligned.m8n8.x4.shared.b16 {%0,%1,%2,%3}, [%4];" \
        : "=r"((r)[0]), "=r"((r)[1]), "=r"((r)[2]), "=r"((r)[3]) : "r"(addr))
#define MMA_F16(C, A, b0, b1) \
    asm volatile("mma.sync.aligned.m16n8k16.row.col.f32.f16.f16.f32 " \
        "{%0,%1,%2,%3},{%4,%5,%6,%7},{%8,%9},{%0,%1,%2,%3};" \
        : "+f"((C)[0]), "+f"((C)[1]), "+f"((C)[2]), "+f"((C)[3]) \
        : "r"((A)[0]), "r"((A)[1]), "r"((A)[2]), "r"((A)[3]), "r"(b0), "r"(b1))
#define CP_ASYNC16(dst, src) \
    asm volatile("cp.async.ca.shared.global [%0], [%1], 16;" :: "r"(dst), "l"(src))
#define CP_COMMIT() asm volatile("cp.async.commit_group;")
#define CP_WAIT_ALL() asm volatile("cp.async.wait_all;")
// NOTE: parameter names must not collide with float4 member names
#define FMA4(accv, sclr, wvec) { (accv).x += (sclr)*(wvec).x; \
                                 (accv).y += (sclr)*(wvec).y; \
                                 (accv).z += (sclr)*(wvec).z; \
                                 (accv).w += (sclr)*(wvec).w; }

__device__ __forceinline__ void split16(float v, __half& a, __half& b) {
    a = __float2half(v);
    b = __float2half(v - __half2float(a));
}

// ---------------- K1: fused projections (nodes + edges) --------------------
__global__ void k_proj(const float* __restrict__ nf,
                       const float* __restrict__ Wp,
                       const float* __restrict__ bp,
                       const float* __restrict__ ea,
                       const float* __restrict__ Wpe,
                       const float* __restrict__ bpe) {
    __shared__ float s[256];
    int tid = threadIdx.x;
    if (blockIdx.x < 1024) {
        int n0 = blockIdx.x * 4;
        s[tid] = nf[(size_t)n0 * 64 + tid];
        __syncthreads();
        int nl = tid >> 6, c = tid & 63;
        float sum = bp[c];
#pragma unroll 16
        for (int k = 0; k < 64; k++) sum += s[nl * 64 + k] * Wp[k * 64 + c];
        float v = fmaxf(sum, 0.f);
        size_t o = (size_t)(n0 + nl) * 64 + c;
        g_h[o] = v;
        __half a, b; split16(v, a, b);
        g_h1[o] = a; g_h2[o] = b;
    } else {
        int e0 = (blockIdx.x - 1024) * 2;
        if (tid < 32) s[tid] = ea[(size_t)e0 * 16 + tid];
        __syncthreads();
        int el = tid >> 7, c = tid & 127;
        float sum = bpe[c];
#pragma unroll
        for (int k = 0; k < 16; k++) sum += s[el * 16 + k] * Wpe[k * 128 + c];
        float v = fmaxf(sum, 0.f);
        size_t idx = (size_t)(e0 + el) * 128 + c;
        g_e[idx] = v;
        __half a, b; split16(v, a, b);
        g_e1[idx] = a; g_e2[idx] = b;
    }
}

// ---------------- fused weight transpose + fp16 limb split -----------------
__global__ void k_split_all(const float* __restrict__ Wnn,
                            const float* __restrict__ We1,
                            const float* __restrict__ We2) {
    __shared__ float t[32][33];
    int x = threadIdx.x, y = threadIdx.y;           // 32 x 8
    int b = blockIdx.x;
    const float* W; int K, N, sel, bx, by;
    if (b < 512)      { W = Wnn; K = 128; N = 4096; sel = 0; bx = b & 127; by = b >> 7; }
    else if (b < 544) { b -= 512; W = We1; K = 256; N = 128; sel = 1; bx = b & 3; by = b >> 2; }
    else              { b -= 544; W = We2; K = 128; N = 128; sel = 2; bx = b & 3; by = b >> 2; }
    int nb = bx * 32, kb = by * 32;
#pragma unroll
    for (int i = 0; i < 4; i++)
        t[y + 8 * i][x] = W[(size_t)(kb + y + 8 * i) * N + nb + x];
    __syncthreads();
    __half* d1 = (sel == 0) ? g_Wt1 : (sel == 1) ? g_We1T1 : g_We2T1;
    __half* d2 = (sel == 1) ? g_We1T2 : g_We2T2;
#pragma unroll
    for (int i = 0; i < 4; i++) {
        float v = t[x][y + 8 * i];
        size_t o = (size_t)(nb + y + 8 * i) * K + kb + x;
        __half a, b2; split16(v, a, b2);
        d1[o] = a;
        if (sel != 0) d2[o] = b2;
    }
}

// ---------------- K4: NNConv, fp16 single-pass mma, n-split x4 -------------
#define NC_SMEM 55808
#define OFF_BIAS 1024
#define OFF_HS   5120
#define OFF_AB   38400
extern "C" __global__ void __launch_bounds__(256, 3)
k_nnconv_mma(const int* __restrict__ eidx, const float* __restrict__ b_nn) {
    extern __shared__ char sm[];
    int* sc = (int*)sm;
    int* tcs = (int*)(sm + 512);
    float* sbias = (float*)(sm + OFF_BIAS);
    float* hs = (float*)(sm + OFF_HS);
    char* AB = sm + OFF_AB;
    const uint32_t ABu = smem_u32(AB);

    const int tid = threadIdx.x;
    const int q = blockIdx.x & 3;
    const int e0 = (blockIdx.x >> 2) * 128;
    const int ncol0 = q * 16;
    const int w = tid >> 5, lane = tid & 31;

    if (tid < 128) sc[tid] = eidx[e0 + tid];
    else           tcs[tid - 128] = eidx[N_EDGES + e0 + (tid - 128)];
    {
        int d = tid >> 2, jq = tid & 3;
        *(float4*)(sbias + d * 16 + jq * 4) =
            *(const float4*)(b_nn + d * 64 + ncol0 + jq * 4);
    }
    __syncthreads();

    {
        int l = tid >> 1, d0 = (tid & 1) * 32;
        const float* hrow = g_h + (size_t)sc[l] * 64 + d0;
        float* dst = hs + l * 65 + d0;
#pragma unroll
        for (int i = 0; i < 32; i += 4) {
            float4 v = *(const float4*)(hrow + i);
            dst[i] = v.x; dst[i + 1] = v.y; dst[i + 2] = v.z; dst[i + 3] = v.w;
        }
    }

    uint32_t a1[8][4];
    {
        const uint4* s1 = (const uint4*)(g_e1 + (size_t)e0 * 128);
#pragma unroll
        for (int r = 0; r < 2; r++) {
            __syncthreads();
#pragma unroll
            for (int it = 0; it < 4; it++) {
                int idx = it * 256 + tid;
                int row = idx >> 4, sl = idx & 15;
                *(uint4*)(AB + row * 272 + sl * 16) = s1[(64 * r + row) * 16 + sl];
            }
            __syncthreads();
            if ((w >> 2) == r) {
                uint32_t base = ABu + (uint32_t)((16 * (w & 3) + (lane & 15)) * 272 +
                                                 (lane >> 4) * 16);
#pragma unroll
                for (int kf = 0; kf < 8; kf++) LDSM4(a1[kf], base + kf * 32);
            }
        }
        __syncthreads();
    }

    {
        int row = tid >> 4, sl = tid & 15;
        CP_ASYNC16(ABu + row * 272 + sl * 16,
                   g_Wt1 + (size_t)(ncol0 + row) * 128 + sl * 8);
    }
    CP_COMMIT();

    const int gid = lane >> 2, tpair = (lane & 3) * 2;
    const int row0 = 16 * w + gid;
    const float* hvp0 = hs + row0 * 65;
    const float* hvp1 = hs + (row0 + 8) * 65;
    const uint32_t boff = (uint32_t)((lane & 7) * 272 + ((lane >> 3) & 1) * 16 +
                                     (lane >> 4) * 2176);
    float msg[2][4] = {};

    for (int d = 0; d < 64; d++) {
        CP_WAIT_ALL();
        __syncthreads();
        if (d + 1 < 64) {
            int row = tid >> 4, sl = tid & 15;
            CP_ASYNC16(ABu + ((d + 1) & 1) * 4352 + row * 272 + sl * 16,
                       g_Wt1 + (size_t)((d + 1) * 64 + ncol0 + row) * 128 + sl * 8);
            CP_COMMIT();
        }

        float C[2][4];
        const float* bptr = sbias + d * 16 + tpair;
#pragma unroll
        for (int nf = 0; nf < 2; nf++) {
            float2 bv = *(const float2*)(bptr + nf * 8);
            C[nf][0] = bv.x; C[nf][1] = bv.y;
            C[nf][2] = bv.x; C[nf][3] = bv.y;
        }
        const uint32_t bb = ABu + (d & 1) * 4352 + boff;
#pragma unroll
        for (int kf = 0; kf < 8; kf++) {
            uint32_t b[4];
            LDSM4(b, bb + kf * 32);
            MMA_F16(C[0], a1[kf], b[0], b[1]);
            MMA_F16(C[1], a1[kf], b[2], b[3]);
        }
        float hv0 = hvp0[d], hv1 = hvp1[d];
#pragma unroll
        for (int nf = 0; nf < 2; nf++) {
            msg[nf][0] = fmaf(hv0, fmaxf(C[nf][0], 0.f), msg[nf][0]);
            msg[nf][1] = fmaf(hv0, fmaxf(C[nf][1], 0.f), msg[nf][1]);
            msg[nf][2] = fmaf(hv1, fmaxf(C[nf][2], 0.f), msg[nf][2]);
            msg[nf][3] = fmaf(hv1, fmaxf(C[nf][3], 0.f), msg[nf][3]);
        }
    }

    float* d0 = g_agg + (size_t)tcs[row0] * 64 + ncol0 + tpair;
    float* d1 = g_agg + (size_t)tcs[row0 + 8] * 64 + ncol0 + tpair;
#pragma unroll
    for (int nf = 0; nf < 2; nf++) {
        atomicAdd(d0 + nf * 8,     msg[nf][0]);
        atomicAdd(d0 + nf * 8 + 1, msg[nf][1]);
        atomicAdd(d1 + nf * 8,     msg[nf][2]);
        atomicAdd(d1 + nf * 8 + 1, msg[nf][3]);
    }
}

// ---------------- K5+K6: conv + GRU, broadcast-weight layout ----------------
// grid 128 x 256thr, 32 nodes/CTA. Warp-per-columns, lane-per-node:
// weight LDS are warp-broadcast (1 transaction); h/m in stride-65 smem
// (conflict-free scalar access). Bitwise-identical accumulation order.
// smem floats: Wr@0(4096) Wih@4096(12288) Whh@16384(12288)
//   shr@28672(2080,str65) smm@30752(2080) sgi@32832(6272,str196) sgh@39104
//   total 45376 floats = 181504 B
#define CG_SMEM 181504
__global__ void __launch_bounds__(256, 1)
k_conv_gru(const float* __restrict__ Wr,  const float* __restrict__ bc,
           const float* __restrict__ wih, const float* __restrict__ whh,
           const float* __restrict__ bih, const float* __restrict__ bhh,
           float* __restrict__ outp) {
    extern __shared__ float s[];
    float* sWr  = s;
    float* sWih = s + 4096;
    float* sWhh = s + 16384;
    float* shr  = s + 28672;   // [n*65 + k]
    float* smm  = s + 30752;   // [n*65 + k]
    float* sgi  = s + 32832;   // [n*196 + c]
    float* sgh  = s + 39104;

    const int tid = threadIdx.x;
    const int n0 = blockIdx.x * 32;
    const int w = tid >> 5, lane = tid & 31;   // lane = node

    // weights -> smem
    for (int i = tid; i < 1024; i += 256)
        ((float4*)sWr)[i] = ((const float4*)Wr)[i];
    for (int i = tid; i < 3072; i += 256) {
        ((float4*)sWih)[i] = ((const float4*)wih)[i];
        ((float4*)sWhh)[i] = ((const float4*)whh)[i];
    }
    // h rows -> shr (stride 65, scalar stores)
    for (int i = tid; i < 256; i += 256) ;   // (no-op keeps structure clear)
    {
        int n = tid >> 3, c8 = (tid & 7) * 8;
        float4 va = *(const float4*)(g_h + (size_t)(n0 + n) * 64 + c8);
        float4 vb = *(const float4*)(g_h + (size_t)(n0 + n) * 64 + c8 + 4);
        float* dst = shr + n * 65 + c8;
        dst[0] = va.x; dst[1] = va.y; dst[2] = va.z; dst[3] = va.w;
        dst[4] = vb.x; dst[5] = vb.y; dst[6] = vb.z; dst[7] = vb.w;
    }
    __syncthreads();

    // ---- phase A: m = relu(agg + h@Wr + bc); warp w -> cols 8w..8w+7
    {
        const int cb = w * 8;
        float* aggp = g_agg + (size_t)(n0 + lane) * 64 + cb;
        float4 acc0 = *(const float4*)aggp;
        float4 acc1 = *(const float4*)(aggp + 4);
        *(float4*)aggp = make_float4(0.f, 0.f, 0.f, 0.f);
        *(float4*)(aggp + 4) = make_float4(0.f, 0.f, 0.f, 0.f);
        float4 bc0 = *(const float4*)(bc + cb);
        float4 bc1 = *(const float4*)(bc + cb + 4);
        acc0.x += bc0.x; acc0.y += bc0.y; acc0.z += bc0.z; acc0.w += bc0.w;
        acc1.x += bc1.x; acc1.y += bc1.y; acc1.z += bc1.z; acc1.w += bc1.w;
        const float* hp = shr + lane * 65;
#pragma unroll 4
        for (int k = 0; k < 64; k++) {
            float hv = hp[k];
            float4 wv0 = *(const float4*)(sWr + k * 64 + cb);       // broadcast
            float4 wv1 = *(const float4*)(sWr + k * 64 + cb + 4);   // broadcast
            FMA4(acc0, hv, wv0);
            FMA4(acc1, hv, wv1);
        }
        float* mp = smm + lane * 65 + cb;
        mp[0] = fmaxf(acc0.x, 0.f); mp[1] = fmaxf(acc0.y, 0.f);
        mp[2] = fmaxf(acc0.z, 0.f); mp[3] = fmaxf(acc0.w, 0.f);
        mp[4] = fmaxf(acc1.x, 0.f); mp[5] = fmaxf(acc1.y, 0.f);
        mp[6] = fmaxf(acc1.z, 0.f); mp[7] = fmaxf(acc1.w, 0.f);
    }
    __syncthreads();

    // ---- phase B: warps 0-3: gi = m@wih + bih (cols 48w..48w+47)
    //               warps 4-7: gh = h@whh + bhh (cols 48(w-4)..)
    {
        const int isGh = (w >> 2) & 1;
        const int cb = (w & 3) * 48;
        const float* Wsm = isGh ? sWhh : sWih;
        const float* bias = isGh ? bhh : bih;
        const float* src = (isGh ? shr : smm) + lane * 65;
        float* dst = (isGh ? sgh : sgi) + lane * 196 + cb;
        float4 acc[12];
#pragma unroll
        for (int j = 0; j < 12; j++)
            acc[j] = *(const float4*)(bias + cb + j * 4);    // broadcast
#pragma unroll 2
        for (int k = 0; k < 64; k++) {
            float v = src[k];
            const float* wr = Wsm + k * 192 + cb;
#pragma unroll
            for (int j = 0; j < 12; j++) {
                float4 wv = *(const float4*)(wr + j * 4);    // broadcast
                FMA4(acc[j], v, wv);
            }
        }
#pragma unroll
        for (int j = 0; j < 12; j++)
            *(float4*)(dst + j * 4) = acc[j];
    }
    __syncthreads();

    // ---- gates ----
    for (int i = tid; i < 2048; i += 256) {
        int n = i >> 6, c = i & 63;
        const float* gi = sgi + n * 196;
        const float* gh = sgh + n * 196;
        float r = 1.f / (1.f + expf(-(gi[c] + gh[c])));
        float z = 1.f / (1.f + expf(-(gi[64 + c] + gh[64 + c])));
        float nc = tanhf(gi[128 + c] + r * gh[128 + c]);
        float v = (1.f - z) * nc + z * shr[n * 65 + c];
        size_t o = (size_t)(n0 + n) * 64 + c;
        g_h[o] = v;
        if (outp) outp[o] = v;
        __half a, b; split16(v, a, b);
        g_h1[o] = a; g_h2[o] = b;
    }
}

// ---------------- K7: edge-update MLP, 32-edge CTAs, occ 2 -----------------
#define EU_SMEM   104960
#define EU_OFF_A  1536
#define EU_A_PL   16896
#define EU_OFF_B  35328
#define EU_T_PL   8704
#define EU_B2_PL  34816
extern "C" __global__ void __launch_bounds__(256, 2)
k_edgeup_tc(const int* __restrict__ eidx,
            const float* __restrict__ b1, const float* __restrict__ b2,
            float* __restrict__ oute) {
    extern __shared__ char sm[];
    const uint32_t sbase = smem_u32(sm);
    int* sc = (int*)sm;
    int* tcs = (int*)(sm + 128);
    float* b1s = (float*)(sm + 512);
    float* b2s = (float*)(sm + 1024);

    const int tid = threadIdx.x;
    const int e0 = blockIdx.x * 32;
    const int w = tid >> 5, lane = tid & 31;

    if (tid < 32)      sc[tid] = eidx[e0 + tid];
    else if (tid < 64) tcs[tid - 32] = eidx[N_EDGES + e0 + (tid - 32)];
    else if (tid < 192) b1s[tid - 64] = b1[tid - 64];
    else               b2s[tid - 192] = b2[tid - 192];
    if (tid < 64) b2s[64 + tid] = b2[64 + tid];

    for (int i = tid; i < 4096; i += 256) {
        int n = i >> 5, c = i & 31;
        CP_ASYNC16(sbase + EU_OFF_B + n * 528 + c * 16,
                   g_We1T1 + (size_t)n * 256 + c * 8);
    }
    CP_COMMIT();
    __syncthreads();

    for (int i = tid; i < 512; i += 256) {
        int s2 = i >> 8, j = i & 255;
        int l = j >> 3, c = (j & 7) * 8;
        int nrow = s2 ? tcs[l] : sc[l];
        const uint4* s1 = (const uint4*)(g_h1 + (size_t)nrow * 64 + c);
        const uint4* s2p = (const uint4*)(g_h2 + (size_t)nrow * 64 + c);
        char* dst = sm + EU_OFF_A + l * 528 + s2 * 128 + c * 2;
        *(uint4*)dst = *s1;
        *(uint4*)(dst + EU_A_PL) = *s2p;
    }
    for (int i = tid; i < 512; i += 256) {
        int l = i >> 4, c = (i & 15) * 8;
        const uint4* s1 = (const uint4*)(g_e1 + (size_t)(e0 + l) * 128 + c);
        const uint4* s2p = (const uint4*)(g_e2 + (size_t)(e0 + l) * 128 + c);
        char* dst = sm + EU_OFF_A + l * 528 + 256 + c * 2;
        *(uint4*)dst = *s1;
        *(uint4*)(dst + EU_A_PL) = *s2p;
    }
    CP_WAIT_ALL();
    __syncthreads();

    const int mf = w & 1, nh = w >> 1;
    const int nbase = nh * 32;
    const int gid = lane >> 2, tpair = (lane & 3) * 2;
    const uint32_t aoff = (uint32_t)((16 * mf + (lane & 15)) * 528 + (lane >> 4) * 16);
    const uint32_t boff = (uint32_t)((nbase + (lane >> 4) * 8 + (lane & 7)) * 528 +
                                     ((lane >> 3) & 1) * 16);

    float C[4][4];
#pragma unroll
    for (int nf = 0; nf < 4; nf++) {
        float2 bv = *(const float2*)(b1s + nbase + nf * 8 + tpair);
        C[nf][0] = bv.x; C[nf][1] = bv.y;
        C[nf][2] = bv.x; C[nf][3] = bv.y;
    }

#pragma unroll
    for (int kf = 0; kf < 16; kf++) {
        uint32_t fa1[4], fa2[4];
        LDSM4(fa1, sbase + EU_OFF_A + aoff + kf * 32);
        LDSM4(fa2, sbase + EU_OFF_A + EU_A_PL + aoff + kf * 32);
#pragma unroll
        for (int p = 0; p < 2; p++) {
            uint32_t b[4];
            LDSM4(b, sbase + EU_OFF_B + boff + p * 8448 + kf * 32);
            MMA_F16(C[2 * p],     fa1, b[0], b[1]);
            MMA_F16(C[2 * p],     fa2, b[0], b[1]);
            MMA_F16(C[2 * p + 1], fa1, b[2], b[3]);
            MMA_F16(C[2 * p + 1], fa2, b[2], b[3]);
        }
    }
    __syncthreads();

    for (int i = tid; i < 4096; i += 256) {
        int n = i >> 5, c = i & 31;
        CP_ASYNC16(sbase + EU_OFF_B + n * 528 + c * 16,
                   g_We1T2 + (size_t)n * 256 + c * 8);
    }
    CP_COMMIT();
    CP_WAIT_ALL();
    __syncthreads();

#pragma unroll
    for (int kf = 0; kf < 16; kf++) {
        uint32_t fa1[4];
        LDSM4(fa1, sbase + EU_OFF_A + aoff + kf * 32);
#pragma unroll
        for (int p = 0; p < 2; p++) {
            uint32_t b[4];
            LDSM4(b, sbase + EU_OFF_B + boff + p * 8448 + kf * 32);
            MMA_F16(C[2 * p],     fa1, b[0], b[1]);
            MMA_F16(C[2 * p + 1], fa1, b[2], b[3]);
        }
    }
    __syncthreads();

    for (int i = tid; i < 4096; i += 256) {
        int p = i >> 11, n = (i >> 4) & 127, c = i & 15;
        const __half* src = (p ? g_We2T2 : g_We2T1) + (size_t)n * 128 + c * 8;
        CP_ASYNC16(sbase + EU_OFF_B + p * EU_B2_PL + n * 272 + c * 16, src);
    }
    CP_COMMIT();

    {
        int r0 = 16 * mf + gid;
#pragma unroll
        for (int nf = 0; nf < 4; nf++) {
            int col = nbase + nf * 8 + tpair;
#pragma unroll
            for (int half = 0; half < 2; half++) {
                int r = r0 + half * 8;
                float v0 = fmaxf(C[nf][2 * half], 0.f);
                float v1 = fmaxf(C[nf][2 * half + 1], 0.f);
                __half a0, c0, a1_, c1;
                split16(v0, a0, c0);
                split16(v1, a1_, c1);
                char* base = sm + EU_OFF_A + r * 272 + col * 2;
                *(__half2*)base = __halves2half2(a0, a1_);
                *(__half2*)(base + EU_T_PL) = __halves2half2(c0, c1);
            }
        }
    }
    CP_WAIT_ALL();
    __syncthreads();

    const uint32_t toff = (uint32_t)((16 * mf + (lane & 15)) * 272 + (lane >> 4) * 16);
    const uint32_t b2off = (uint32_t)((nbase + (lane & 7)) * 272 +
                                      ((lane >> 3) & 1) * 16 +
                                      (lane >> 4) * EU_B2_PL);
    float C2[4][4];
#pragma unroll
    for (int nf = 0; nf < 4; nf++) {
        float2 bv = *(const float2*)(b2s + nbase + nf * 8 + tpair);
        C2[nf][0] = bv.x; C2[nf][1] = bv.y;
        C2[nf][2] = bv.x; C2[nf][3] = bv.y;
    }
#pragma unroll
    for (int kf = 0; kf < 8; kf++) {
        uint32_t fa1[4], fa2[4];
        LDSM4(fa1, sbase + EU_OFF_A + toff + kf * 32);
        LDSM4(fa2, sbase + EU_OFF_A + EU_T_PL + toff + kf * 32);
#pragma unroll
        for (int nf = 0; nf < 4; nf++) {
            uint32_t b[4];
            LDSM4(b, sbase + EU_OFF_B + b2off + nf * 2176 + kf * 32);
            MMA_F16(C2[nf], fa1, b[0], b[1]);
            MMA_F16(C2[nf], fa2, b[0], b[1]);
            MMA_F16(C2[nf], fa1, b[2], b[3]);
        }
    }

    {
        int r0 = 16 * mf + gid;
#pragma unroll
        for (int nf = 0; nf < 4; nf++) {
            int col = nbase + nf * 8 + tpair;
#pragma unroll
            for (int half = 0; half < 2; half++) {
                int r = r0 + half * 8;
                size_t o = (size_t)(e0 + r) * 128 + col;
                float v0 = fmaxf(C2[nf][2 * half], 0.f);
                float v1 = fmaxf(C2[nf][2 * half + 1], 0.f);
                g_e[o] = v0; g_e[o + 1] = v1;
                if (oute) { oute[o] = v0; oute[o + 1] = v1; }
                __half a0, c0, a1_, c1;
                split16(v0, a0, c0);
                split16(v1, a1_, c1);
                *(__half2*)(g_e1 + o) = __halves2half2(a0, a1_);
                *(__half2*)(g_e2 + o) = __halves2half2(c0, c1);
            }
        }
    }
}

// ---------------- launcher -------------------------------------------------
extern "C" void kernel_launch(void* const* d_in, const int* in_sizes, int n_in,
                              void* d_out, int out_size) {
    const float* nf   = (const float*)d_in[0];
    const float* ea   = (const float*)d_in[1];
    const int*   eidx = (const int*)  d_in[2];
    const float* Wp   = (const float*)d_in[3];
    const float* bp   = (const float*)d_in[4];
    const float* Wpe  = (const float*)d_in[5];
    const float* bpe  = (const float*)d_in[6];
    const float* Wnn  = (const float*)d_in[7];
    const float* bnn  = (const float*)d_in[8];
    const float* Wr   = (const float*)d_in[9];
    const float* bc   = (const float*)d_in[10];
    const float* wih  = (const float*)d_in[11];
    const float* whh  = (const float*)d_in[12];
    const float* bih  = (const float*)d_in[13];
    const float* bhh  = (const float*)d_in[14];
    const float* We1  = (const float*)d_in[15];
    const float* be1  = (const float*)d_in[16];
    const float* We2  = (const float*)d_in[17];
    const float* be2  = (const float*)d_in[18];

    float* out_h = (float*)d_out;
    float* out_e = (float*)d_out + (size_t)N_NODES * DIM;

    cudaFuncSetAttribute(k_nnconv_mma, cudaFuncAttributeMaxDynamicSharedMemorySize, NC_SMEM);
    cudaFuncSetAttribute(k_edgeup_tc, cudaFuncAttributeMaxDynamicSharedMemorySize, EU_SMEM);
    cudaFuncSetAttribute(k_conv_gru, cudaFuncAttributeMaxDynamicSharedMemorySize, CG_SMEM);

    k_split_all<<<560, dim3(32, 8)>>>(Wnn, We1, We2);
    k_proj<<<1024 + N_EDGES / 2, 256>>>(nf, Wp, bp, ea, Wpe, bpe);

    for (int step = 0; step < NUM_STEPS; step++) {
        bool last = (step == NUM_STEPS - 1);
        k_nnconv_mma<<<(N_EDGES / 128) * 4, 256, NC_SMEM>>>(eidx, bnn);
        k_conv_gru<<<N_NODES / 32, 256, CG_SMEM>>>(Wr, bc, wih, whh, bih, bhh,
                                                   last ? out_h : (float*)nullptr);
        k_edgeup_tc<<<N_EDGES / 32, 256, EU_SMEM>>>(eidx, be1, be2,
                                                    last ? out_e : (float*)nullptr);
    }
}

// round 11
// speedup vs baseline: 1.0071x; 1.0071x over previous
#include <cuda_runtime.h>
#include <cuda_fp16.h>
#include <math.h>
#include <stdint.h>

#define N_NODES 4096
#define N_EDGES 32768
#define DIM 64
#define EHID 128
#define NUM_STEPS 3

// ---------------- scratch (device globals; zero-initialized) ----------------
__device__ float g_h[N_NODES * DIM];
__device__ float g_e[N_EDGES * EHID];
__device__ float g_agg[N_NODES * DIM];    // invariant: zero at kernel_launch entry
__device__ __half g_h1[N_NODES * DIM];
__device__ __half g_h2[N_NODES * DIM];
__device__ __half g_e1[N_EDGES * EHID];
__device__ __half g_e2[N_EDGES * EHID];
__device__ __half g_Wt1[4096 * 128];      // W_nn^T [n][k] limb1
__device__ __half g_We1T1[128 * 256];
__device__ __half g_We1T2[128 * 256];
__device__ __half g_We2T1[128 * 128];
__device__ __half g_We2T2[128 * 128];

// ---------------- helpers ---------------------------------------------------
__device__ __forceinline__ uint32_t smem_u32(const void* p) {
    uint32_t a;
    asm("{ .reg .u64 t; cvta.to.shared.u64 t, %1; cvt.u32.u64 %0, t; }"
        : "=r"(a) : "l"(p));
    return a;
}
#define LDSM4(r, addr) \
    asm volatile("ldmatrix.sync.aligned.m8n8.x4.shared.b16 {%0,%1,%2,%3}, [%4];" \
        : "=r"((r)[0]), "=r"((r)[1]), "=r"((r)[2]), "=r"((r)[3]) : "r"(addr))
#define MMA_F16(C, A, b0, b1) \
    asm volatile("mma.sync.aligned.m16n8k16.row.col.f32.f16.f16.f32 " \
        "{%0,%1,%2,%3},{%4,%5,%6,%7},{%8,%9},{%0,%1,%2,%3};" \
        : "+f"((C)[0]), "+f"((C)[1]), "+f"((C)[2]), "+f"((C)[3]) \
        : "r"((A)[0]), "r"((A)[1]), "r"((A)[2]), "r"((A)[3]), "r"(b0), "r"(b1))
#define CP_ASYNC16(dst, src) \
    asm volatile("cp.async.ca.shared.global [%0], [%1], 16;" :: "r"(dst), "l"(src))
#define CP_COMMIT() asm volatile("cp.async.commit_group;")
#define CP_WAIT_ALL() asm volatile("cp.async.wait_all;")
// NOTE: parameter names must not collide with float4 member names
#define FMA4(accv, sclr, wvec) { (accv).x += (sclr)*(wvec).x; \
                                 (accv).y += (sclr)*(wvec).y; \
                                 (accv).z += (sclr)*(wvec).z; \
                                 (accv).w += (sclr)*(wvec).w; }

__device__ __forceinline__ void split16(float v, __half& a, __half& b) {
    a = __float2half(v);
    b = __float2half(v - __half2float(a));
}

// ---------------- K1: fused projections (nodes + edges) --------------------
__global__ void k_proj(const float* __restrict__ nf,
                       const float* __restrict__ Wp,
                       const float* __restrict__ bp,
                       const float* __restrict__ ea,
                       const float* __restrict__ Wpe,
                       const float* __restrict__ bpe) {
    __shared__ float s[256];
    int tid = threadIdx.x;
    if (blockIdx.x < 1024) {
        int n0 = blockIdx.x * 4;
        s[tid] = nf[(size_t)n0 * 64 + tid];
        __syncthreads();
        int nl = tid >> 6, c = tid & 63;
        float sum = bp[c];
#pragma unroll 16
        for (int k = 0; k < 64; k++) sum += s[nl * 64 + k] * Wp[k * 64 + c];
        float v = fmaxf(sum, 0.f);
        size_t o = (size_t)(n0 + nl) * 64 + c;
        g_h[o] = v;
        __half a, b; split16(v, a, b);
        g_h1[o] = a; g_h2[o] = b;
    } else {
        int e0 = (blockIdx.x - 1024) * 2;
        if (tid < 32) s[tid] = ea[(size_t)e0 * 16 + tid];
        __syncthreads();
        int el = tid >> 7, c = tid & 127;
        float sum = bpe[c];
#pragma unroll
        for (int k = 0; k < 16; k++) sum += s[el * 16 + k] * Wpe[k * 128 + c];
        float v = fmaxf(sum, 0.f);
        size_t idx = (size_t)(e0 + el) * 128 + c;
        g_e[idx] = v;
        __half a, b; split16(v, a, b);
        g_e1[idx] = a; g_e2[idx] = b;
    }
}

// ---------------- fused weight transpose + fp16 limb split -----------------
__global__ void k_split_all(const float* __restrict__ Wnn,
                            const float* __restrict__ We1,
                            const float* __restrict__ We2) {
    __shared__ float t[32][33];
    int x = threadIdx.x, y = threadIdx.y;           // 32 x 8
    int b = blockIdx.x;
    const float* W; int K, N, sel, bx, by;
    if (b < 512)      { W = Wnn; K = 128; N = 4096; sel = 0; bx = b & 127; by = b >> 7; }
    else if (b < 544) { b -= 512; W = We1; K = 256; N = 128; sel = 1; bx = b & 3; by = b >> 2; }
    else              { b -= 544; W = We2; K = 128; N = 128; sel = 2; bx = b & 3; by = b >> 2; }
    int nb = bx * 32, kb = by * 32;
#pragma unroll
    for (int i = 0; i < 4; i++)
        t[y + 8 * i][x] = W[(size_t)(kb + y + 8 * i) * N + nb + x];
    __syncthreads();
    __half* d1 = (sel == 0) ? g_Wt1 : (sel == 1) ? g_We1T1 : g_We2T1;
    __half* d2 = (sel == 1) ? g_We1T2 : g_We2T2;
#pragma unroll
    for (int i = 0; i < 4; i++) {
        float v = t[x][y + 8 * i];
        size_t o = (size_t)(nb + y + 8 * i) * K + kb + x;
        __half a, b2; split16(v, a, b2);
        d1[o] = a;
        if (sel != 0) d2[o] = b2;
    }
}

// ---------------- K4: NNConv, fp16 single-pass mma, n-split x4 -------------
#define NC_SMEM 55808
#define OFF_BIAS 1024
#define OFF_HS   5120
#define OFF_AB   38400
extern "C" __global__ void __launch_bounds__(256, 3)
k_nnconv_mma(const int* __restrict__ eidx, const float* __restrict__ b_nn) {
    extern __shared__ char sm[];
    int* sc = (int*)sm;
    int* tcs = (int*)(sm + 512);
    float* sbias = (float*)(sm + OFF_BIAS);
    float* hs = (float*)(sm + OFF_HS);
    char* AB = sm + OFF_AB;
    const uint32_t ABu = smem_u32(AB);

    const int tid = threadIdx.x;
    const int q = blockIdx.x & 3;
    const int e0 = (blockIdx.x >> 2) * 128;
    const int ncol0 = q * 16;
    const int w = tid >> 5, lane = tid & 31;

    if (tid < 128) sc[tid] = eidx[e0 + tid];
    else           tcs[tid - 128] = eidx[N_EDGES + e0 + (tid - 128)];
    {
        int d = tid >> 2, jq = tid & 3;
        *(float4*)(sbias + d * 16 + jq * 4) =
            *(const float4*)(b_nn + d * 64 + ncol0 + jq * 4);
    }
    __syncthreads();

    {
        int l = tid >> 1, d0 = (tid & 1) * 32;
        const float* hrow = g_h + (size_t)sc[l] * 64 + d0;
        float* dst = hs + l * 65 + d0;
#pragma unroll
        for (int i = 0; i < 32; i += 4) {
            float4 v = *(const float4*)(hrow + i);
            dst[i] = v.x; dst[i + 1] = v.y; dst[i + 2] = v.z; dst[i + 3] = v.w;
        }
    }

    uint32_t a1[8][4];
    {
        const uint4* s1 = (const uint4*)(g_e1 + (size_t)e0 * 128);
#pragma unroll
        for (int r = 0; r < 2; r++) {
            __syncthreads();
#pragma unroll
            for (int it = 0; it < 4; it++) {
                int idx = it * 256 + tid;
                int row = idx >> 4, sl = idx & 15;
                *(uint4*)(AB + row * 272 + sl * 16) = s1[(64 * r + row) * 16 + sl];
            }
            __syncthreads();
            if ((w >> 2) == r) {
                uint32_t base = ABu + (uint32_t)((16 * (w & 3) + (lane & 15)) * 272 +
                                                 (lane >> 4) * 16);
#pragma unroll
                for (int kf = 0; kf < 8; kf++) LDSM4(a1[kf], base + kf * 32);
            }
        }
        __syncthreads();
    }

    {
        int row = tid >> 4, sl = tid & 15;
        CP_ASYNC16(ABu + row * 272 + sl * 16,
                   g_Wt1 + (size_t)(ncol0 + row) * 128 + sl * 8);
    }
    CP_COMMIT();

    const int gid = lane >> 2, tpair = (lane & 3) * 2;
    const int row0 = 16 * w + gid;
    const float* hvp0 = hs + row0 * 65;
    const float* hvp1 = hs + (row0 + 8) * 65;
    const uint32_t boff = (uint32_t)((lane & 7) * 272 + ((lane >> 3) & 1) * 16 +
                                     (lane >> 4) * 2176);
    float msg[2][4] = {};

    for (int d = 0; d < 64; d++) {
        CP_WAIT_ALL();
        __syncthreads();
        if (d + 1 < 64) {
            int row = tid >> 4, sl = tid & 15;
            CP_ASYNC16(ABu + ((d + 1) & 1) * 4352 + row * 272 + sl * 16,
                       g_Wt1 + (size_t)((d + 1) * 64 + ncol0 + row) * 128 + sl * 8);
            CP_COMMIT();
        }

        float C[2][4];
        const float* bptr = sbias + d * 16 + tpair;
#pragma unroll
        for (int nf = 0; nf < 2; nf++) {
            float2 bv = *(const float2*)(bptr + nf * 8);
            C[nf][0] = bv.x; C[nf][1] = bv.y;
            C[nf][2] = bv.x; C[nf][3] = bv.y;
        }
        const uint32_t bb = ABu + (d & 1) * 4352 + boff;
#pragma unroll
        for (int kf = 0; kf < 8; kf++) {
            uint32_t b[4];
            LDSM4(b, bb + kf * 32);
            MMA_F16(C[0], a1[kf], b[0], b[1]);
            MMA_F16(C[1], a1[kf], b[2], b[3]);
        }
        float hv0 = hvp0[d], hv1 = hvp1[d];
#pragma unroll
        for (int nf = 0; nf < 2; nf++) {
            msg[nf][0] = fmaf(hv0, fmaxf(C[nf][0], 0.f), msg[nf][0]);
            msg[nf][1] = fmaf(hv0, fmaxf(C[nf][1], 0.f), msg[nf][1]);
            msg[nf][2] = fmaf(hv1, fmaxf(C[nf][2], 0.f), msg[nf][2]);
            msg[nf][3] = fmaf(hv1, fmaxf(C[nf][3], 0.f), msg[nf][3]);
        }
    }

    float* d0 = g_agg + (size_t)tcs[row0] * 64 + ncol0 + tpair;
    float* d1 = g_agg + (size_t)tcs[row0 + 8] * 64 + ncol0 + tpair;
#pragma unroll
    for (int nf = 0; nf < 2; nf++) {
        atomicAdd(d0 + nf * 8,     msg[nf][0]);
        atomicAdd(d0 + nf * 8 + 1, msg[nf][1]);
        atomicAdd(d1 + nf * 8,     msg[nf][2]);
        atomicAdd(d1 + nf * 8 + 1, msg[nf][3]);
    }
}

// ---------------- K5+K6: conv + GRU, 512 threads, overlapped phases --------
// grid 128 x 512thr, 32 nodes/CTA, 16 warps (4/SMSP for latency hiding).
// Warps 0-7: phase A (m = relu(agg + h@Wr + bc), 8 cols each).
// Warps 8-15 CONCURRENTLY: gh = h@whh + bhh (24 cols each; needs only h).
// Then all 16 warps: gi = m@wih + bih (12 cols each). Weight LDS are
// warp-broadcast; h/m scalar reads from stride-65 smem (conflict-free).
// Accumulation order per column unchanged (bias-first, k-ascending).
// smem floats: Wr@0(4096) Wih@4096(12288) Whh@16384(12288)
//   shr@28672(2080,str65) smm@30752(2080) sgi@32832(6272,str196) sgh@39104
//   total 45376 floats = 181504 B
#define CG_SMEM 181504
__global__ void __launch_bounds__(512, 1)
k_conv_gru(const float* __restrict__ Wr,  const float* __restrict__ bc,
           const float* __restrict__ wih, const float* __restrict__ whh,
           const float* __restrict__ bih, const float* __restrict__ bhh,
           float* __restrict__ outp) {
    extern __shared__ float s[];
    float* sWr  = s;
    float* sWih = s + 4096;
    float* sWhh = s + 16384;
    float* shr  = s + 28672;   // [n*65 + k]
    float* smm  = s + 30752;   // [n*65 + k]
    float* sgi  = s + 32832;   // [n*196 + c]
    float* sgh  = s + 39104;

    const int tid = threadIdx.x;
    const int n0 = blockIdx.x * 32;
    const int w = tid >> 5, lane = tid & 31;   // lane = node

    // weights -> smem (512 threads)
    for (int i = tid; i < 1024; i += 512)
        ((float4*)sWr)[i] = ((const float4*)Wr)[i];
    for (int i = tid; i < 3072; i += 512) {
        ((float4*)sWih)[i] = ((const float4*)wih)[i];
        ((float4*)sWhh)[i] = ((const float4*)whh)[i];
    }
    // h rows -> shr (stride 65, scalar stores); threads 0-255 only
    if (tid < 256) {
        int n = tid >> 3, c8 = (tid & 7) * 8;
        float4 va = *(const float4*)(g_h + (size_t)(n0 + n) * 64 + c8);
        float4 vb = *(const float4*)(g_h + (size_t)(n0 + n) * 64 + c8 + 4);
        float* dst = shr + n * 65 + c8;
        dst[0] = va.x; dst[1] = va.y; dst[2] = va.z; dst[3] = va.w;
        dst[4] = vb.x; dst[5] = vb.y; dst[6] = vb.z; dst[7] = vb.w;
    }
    __syncthreads();

    if (w < 8) {
        // ---- phase A: m = relu(agg + h@Wr + bc); warp w -> cols 8w..8w+7
        const int cb = w * 8;
        float* aggp = g_agg + (size_t)(n0 + lane) * 64 + cb;
        float4 acc0 = *(const float4*)aggp;
        float4 acc1 = *(const float4*)(aggp + 4);
        *(float4*)aggp = make_float4(0.f, 0.f, 0.f, 0.f);
        *(float4*)(aggp + 4) = make_float4(0.f, 0.f, 0.f, 0.f);
        float4 bc0 = *(const float4*)(bc + cb);
        float4 bc1 = *(const float4*)(bc + cb + 4);
        acc0.x += bc0.x; acc0.y += bc0.y; acc0.z += bc0.z; acc0.w += bc0.w;
        acc1.x += bc1.x; acc1.y += bc1.y; acc1.z += bc1.z; acc1.w += bc1.w;
        const float* hp = shr + lane * 65;
#pragma unroll 4
        for (int k = 0; k < 64; k++) {
            float hv = hp[k];
            float4 wv0 = *(const float4*)(sWr + k * 64 + cb);       // broadcast
            float4 wv1 = *(const float4*)(sWr + k * 64 + cb + 4);   // broadcast
            FMA4(acc0, hv, wv0);
            FMA4(acc1, hv, wv1);
        }
        float* mp = smm + lane * 65 + cb;
        mp[0] = fmaxf(acc0.x, 0.f); mp[1] = fmaxf(acc0.y, 0.f);
        mp[2] = fmaxf(acc0.z, 0.f); mp[3] = fmaxf(acc0.w, 0.f);
        mp[4] = fmaxf(acc1.x, 0.f); mp[5] = fmaxf(acc1.y, 0.f);
        mp[6] = fmaxf(acc1.z, 0.f); mp[7] = fmaxf(acc1.w, 0.f);
    } else {
        // ---- phase gh (concurrent): gh = h@whh + bhh; warp (w-8) -> 24 cols
        const int cb = (w - 8) * 24;
        const float* src = shr + lane * 65;
        float* dst = sgh + lane * 196 + cb;
        float4 acc[6];
#pragma unroll
        for (int j = 0; j < 6; j++)
            acc[j] = *(const float4*)(bhh + cb + j * 4);
#pragma unroll 2
        for (int k = 0; k < 64; k++) {
            float v = src[k];
            const float* wr = sWhh + k * 192 + cb;
#pragma unroll
            for (int j = 0; j < 6; j++) {
                float4 wv = *(const float4*)(wr + j * 4);   // broadcast
                FMA4(acc[j], v, wv);
            }
        }
#pragma unroll
        for (int j = 0; j < 6; j++)
            *(float4*)(dst + j * 4) = acc[j];
    }
    __syncthreads();

    // ---- phase gi: all 16 warps: gi = m@wih + bih; warp w -> 12 cols
    {
        const int cb = w * 12;
        const float* src = smm + lane * 65;
        float* dst = sgi + lane * 196 + cb;
        float4 acc[3];
#pragma unroll
        for (int j = 0; j < 3; j++)
            acc[j] = *(const float4*)(bih + cb + j * 4);
#pragma unroll 4
        for (int k = 0; k < 64; k++) {
            float v = src[k];
            const float* wr = sWih + k * 192 + cb;
#pragma unroll
            for (int j = 0; j < 3; j++) {
                float4 wv = *(const float4*)(wr + j * 4);   // broadcast
                FMA4(acc[j], v, wv);
            }
        }
#pragma unroll
        for (int j = 0; j < 3; j++)
            *(float4*)(dst + j * 4) = acc[j];
    }
    __syncthreads();

    // ---- gates ----
    for (int i = tid; i < 2048; i += 512) {
        int n = i >> 6, c = i & 63;
        const float* gi = sgi + n * 196;
        const float* gh = sgh + n * 196;
        float r = 1.f / (1.f + expf(-(gi[c] + gh[c])));
        float z = 1.f / (1.f + expf(-(gi[64 + c] + gh[64 + c])));
        float nc = tanhf(gi[128 + c] + r * gh[128 + c]);
        float v = (1.f - z) * nc + z * shr[n * 65 + c];
        size_t o = (size_t)(n0 + n) * 64 + c;
        g_h[o] = v;
        if (outp) outp[o] = v;
        __half a, b; split16(v, a, b);
        g_h1[o] = a; g_h2[o] = b;
    }
}

// ---------------- K7: edge-update MLP, 32-edge CTAs, occ 2 -----------------
#define EU_SMEM   104960
#define EU_OFF_A  1536
#define EU_A_PL   16896
#define EU_OFF_B  35328
#define EU_T_PL   8704
#define EU_B2_PL  34816
extern "C" __global__ void __launch_bounds__(256, 2)
k_edgeup_tc(const int* __restrict__ eidx,
            const float* __restrict__ b1, const float* __restrict__ b2,
            float* __restrict__ oute) {
    extern __shared__ char sm[];
    const uint32_t sbase = smem_u32(sm);
    int* sc = (int*)sm;
    int* tcs = (int*)(sm + 128);
    float* b1s = (float*)(sm + 512);
    float* b2s = (float*)(sm + 1024);

    const int tid = threadIdx.x;
    const int e0 = blockIdx.x * 32;
    const int w = tid >> 5, lane = tid & 31;

    if (tid < 32)      sc[tid] = eidx[e0 + tid];
    else if (tid < 64) tcs[tid - 32] = eidx[N_EDGES + e0 + (tid - 32)];
    else if (tid < 192) b1s[tid - 64] = b1[tid - 64];
    else               b2s[tid - 192] = b2[tid - 192];
    if (tid < 64) b2s[64 + tid] = b2[64 + tid];

    for (int i = tid; i < 4096; i += 256) {
        int n = i >> 5, c = i & 31;
        CP_ASYNC16(sbase + EU_OFF_B + n * 528 + c * 16,
                   g_We1T1 + (size_t)n * 256 + c * 8);
    }
    CP_COMMIT();
    __syncthreads();

    for (int i = tid; i < 512; i += 256) {
        int s2 = i >> 8, j = i & 255;
        int l = j >> 3, c = (j & 7) * 8;
        int nrow = s2 ? tcs[l] : sc[l];
        const uint4* s1 = (const uint4*)(g_h1 + (size_t)nrow * 64 + c);
        const uint4* s2p = (const uint4*)(g_h2 + (size_t)nrow * 64 + c);
        char* dst = sm + EU_OFF_A + l * 528 + s2 * 128 + c * 2;
        *(uint4*)dst = *s1;
        *(uint4*)(dst + EU_A_PL) = *s2p;
    }
    for (int i = tid; i < 512; i += 256) {
        int l = i >> 4, c = (i & 15) * 8;
        const uint4* s1 = (const uint4*)(g_e1 + (size_t)(e0 + l) * 128 + c);
        const uint4* s2p = (const uint4*)(g_e2 + (size_t)(e0 + l) * 128 + c);
        char* dst = sm + EU_OFF_A + l * 528 + 256 + c * 2;
        *(uint4*)dst = *s1;
        *(uint4*)(dst + EU_A_PL) = *s2p;
    }
    CP_WAIT_ALL();
    __syncthreads();

    const int mf = w & 1, nh = w >> 1;
    const int nbase = nh * 32;
    const int gid = lane >> 2, tpair = (lane & 3) * 2;
    const uint32_t aoff = (uint32_t)((16 * mf + (lane & 15)) * 528 + (lane >> 4) * 16);
    const uint32_t boff = (uint32_t)((nbase + (lane >> 4) * 8 + (lane & 7)) * 528 +
                                     ((lane >> 3) & 1) * 16);

    float C[4][4];
#pragma unroll
    for (int nf = 0; nf < 4; nf++) {
        float2 bv = *(const float2*)(b1s + nbase + nf * 8 + tpair);
        C[nf][0] = bv.x; C[nf][1] = bv.y;
        C[nf][2] = bv.x; C[nf][3] = bv.y;
    }

#pragma unroll
    for (int kf = 0; kf < 16; kf++) {
        uint32_t fa1[4], fa2[4];
        LDSM4(fa1, sbase + EU_OFF_A + aoff + kf * 32);
        LDSM4(fa2, sbase + EU_OFF_A + EU_A_PL + aoff + kf * 32);
#pragma unroll
        for (int p = 0; p < 2; p++) {
            uint32_t b[4];
            LDSM4(b, sbase + EU_OFF_B + boff + p * 8448 + kf * 32);
            MMA_F16(C[2 * p],     fa1, b[0], b[1]);
            MMA_F16(C[2 * p],     fa2, b[0], b[1]);
            MMA_F16(C[2 * p + 1], fa1, b[2], b[3]);
            MMA_F16(C[2 * p + 1], fa2, b[2], b[3]);
        }
    }
    __syncthreads();

    for (int i = tid; i < 4096; i += 256) {
        int n = i >> 5, c = i & 31;
        CP_ASYNC16(sbase + EU_OFF_B + n * 528 + c * 16,
                   g_We1T2 + (size_t)n * 256 + c * 8);
    }
    CP_COMMIT();
    CP_WAIT_ALL();
    __syncthreads();

#pragma unroll
    for (int kf = 0; kf < 16; kf++) {
        uint32_t fa1[4];
        LDSM4(fa1, sbase + EU_OFF_A + aoff + kf * 32);
#pragma unroll
        for (int p = 0; p < 2; p++) {
            uint32_t b[4];
            LDSM4(b, sbase + EU_OFF_B + boff + p * 8448 + kf * 32);
            MMA_F16(C[2 * p],     fa1, b[0], b[1]);
            MMA_F16(C[2 * p + 1], fa1, b[2], b[3]);
        }
    }
    __syncthreads();

    for (int i = tid; i < 4096; i += 256) {
        int p = i >> 11, n = (i >> 4) & 127, c = i & 15;
        const __half* src = (p ? g_We2T2 : g_We2T1) + (size_t)n * 128 + c * 8;
        CP_ASYNC16(sbase + EU_OFF_B + p * EU_B2_PL + n * 272 + c * 16, src);
    }
    CP_COMMIT();

    {
        int r0 = 16 * mf + gid;
#pragma unroll
        for (int nf = 0; nf < 4; nf++) {
            int col = nbase + nf * 8 + tpair;
#pragma unroll
            for (int half = 0; half < 2; half++) {
                int r = r0 + half * 8;
                float v0 = fmaxf(C[nf][2 * half], 0.f);
                float v1 = fmaxf(C[nf][2 * half + 1], 0.f);
                __half a0, c0, a1_, c1;
                split16(v0, a0, c0);
                split16(v1, a1_, c1);
                char* base = sm + EU_OFF_A + r * 272 + col * 2;
                *(__half2*)base = __halves2half2(a0, a1_);
                *(__half2*)(base + EU_T_PL) = __halves2half2(c0, c1);
            }
        }
    }
    CP_WAIT_ALL();
    __syncthreads();

    const uint32_t toff = (uint32_t)((16 * mf + (lane & 15)) * 272 + (lane >> 4) * 16);
    const uint32_t b2off = (uint32_t)((nbase + (lane & 7)) * 272 +
                                      ((lane >> 3) & 1) * 16 +
                                      (lane >> 4) * EU_B2_PL);
    float C2[4][4];
#pragma unroll
    for (int nf = 0; nf < 4; nf++) {
        float2 bv = *(const float2*)(b2s + nbase + nf * 8 + tpair);
        C2[nf][0] = bv.x; C2[nf][1] = bv.y;
        C2[nf][2] = bv.x; C2[nf][3] = bv.y;
    }
#pragma unroll
    for (int kf = 0; kf < 8; kf++) {
        uint32_t fa1[4], fa2[4];
        LDSM4(fa1, sbase + EU_OFF_A + toff + kf * 32);
        LDSM4(fa2, sbase + EU_OFF_A + EU_T_PL + toff + kf * 32);
#pragma unroll
        for (int nf = 0; nf < 4; nf++) {
            uint32_t b[4];
            LDSM4(b, sbase + EU_OFF_B + b2off + nf * 2176 + kf * 32);
            MMA_F16(C2[nf], fa1, b[0], b[1]);
            MMA_F16(C2[nf], fa2, b[0], b[1]);
            MMA_F16(C2[nf], fa1, b[2], b[3]);
        }
    }

    {
        int r0 = 16 * mf + gid;
#pragma unroll
        for (int nf = 0; nf < 4; nf++) {
            int col = nbase + nf * 8 + tpair;
#pragma unroll
            for (int half = 0; half < 2; half++) {
                int r = r0 + half * 8;
                size_t o = (size_t)(e0 + r) * 128 + col;
                float v0 = fmaxf(C2[nf][2 * half], 0.f);
                float v1 = fmaxf(C2[nf][2 * half + 1], 0.f);
                g_e[o] = v0; g_e[o + 1] = v1;
                if (oute) { oute[o] = v0; oute[o + 1] = v1; }
                __half a0, c0, a1_, c1;
                split16(v0, a0, c0);
                split16(v1, a1_, c1);
                *(__half2*)(g_e1 + o) = __halves2half2(a0, a1_);
                *(__half2*)(g_e2 + o) = __halves2half2(c0, c1);
            }
        }
    }
}

// ---------------- launcher -------------------------------------------------
extern "C" void kernel_launch(void* const* d_in, const int* in_sizes, int n_in,
                              void* d_out, int out_size) {
    const float* nf   = (const float*)d_in[0];
    const float* ea   = (const float*)d_in[1];
    const int*   eidx = (const int*)  d_in[2];
    const float* Wp   = (const float*)d_in[3];
    const float* bp   = (const float*)d_in[4];
    const float* Wpe  = (const float*)d_in[5];
    const float* bpe  = (const float*)d_in[6];
    const float* Wnn  = (const float*)d_in[7];
    const float* bnn  = (const float*)d_in[8];
    const float* Wr   = (const float*)d_in[9];
    const float* bc   = (const float*)d_in[10];
    const float* wih  = (const float*)d_in[11];
    const float* whh  = (const float*)d_in[12];
    const float* bih  = (const float*)d_in[13];
    const float* bhh  = (const float*)d_in[14];
    const float* We1  = (const float*)d_in[15];
    const float* be1  = (const float*)d_in[16];
    const float* We2  = (const float*)d_in[17];
    const float* be2  = (const float*)d_in[18];

    float* out_h = (float*)d_out;
    float* out_e = (float*)d_out + (size_t)N_NODES * DIM;

    cudaFuncSetAttribute(k_nnconv_mma, cudaFuncAttributeMaxDynamicSharedMemorySize, NC_SMEM);
    cudaFuncSetAttribute(k_edgeup_tc, cudaFuncAttributeMaxDynamicSharedMemorySize, EU_SMEM);
    cudaFuncSetAttribute(k_conv_gru, cudaFuncAttributeMaxDynamicSharedMemorySize, CG_SMEM);

    k_split_all<<<560, dim3(32, 8)>>>(Wnn, We1, We2);
    k_proj<<<1024 + N_EDGES / 2, 256>>>(nf, Wp, bp, ea, Wpe, bpe);

    for (int step = 0; step < NUM_STEPS; step++) {
        bool last = (step == NUM_STEPS - 1);
        k_nnconv_mma<<<(N_EDGES / 128) * 4, 256, NC_SMEM>>>(eidx, bnn);
        k_conv_gru<<<N_NODES / 32, 512, CG_SMEM>>>(Wr, bc, wih, whh, bih, bhh,
                                                   last ? out_h : (float*)nullptr);
        k_edgeup_tc<<<N_EDGES / 32, 256, EU_SMEM>>>(eidx, be1, be2,
                                                    last ? out_e : (float*)nullptr);
    }
}

// round 12
// speedup vs baseline: 1.0133x; 1.0061x over previous
#include <cuda_runtime.h>
#include <cuda_fp16.h>
#include <math.h>
#include <stdint.h>

#define N_NODES 4096
#define N_EDGES 32768
#define DIM 64
#define EHID 128
#define NUM_STEPS 3

// ---------------- scratch (device globals; zero-initialized) ----------------
__device__ float g_h[N_NODES * DIM];
__device__ float g_e[N_EDGES * EHID];
__device__ float g_agg[N_NODES * DIM];    // invariant: zero at kernel_launch entry
__device__ __half g_h1[N_NODES * DIM];
__device__ __half g_h2[N_NODES * DIM];
__device__ __half g_e1[N_EDGES * EHID];
__device__ __half g_e2[N_EDGES * EHID];
__device__ __half g_Wt1[4096 * 128];      // W_nn^T [n][k] limb1
__device__ __half g_We1T1[128 * 256];
__device__ __half g_We1T2[128 * 256];
__device__ __half g_We2T1[128 * 128];
__device__ __half g_We2T2[128 * 128];

// ---------------- helpers ---------------------------------------------------
__device__ __forceinline__ uint32_t smem_u32(const void* p) {
    uint32_t a;
    asm("{ .reg .u64 t; cvta.to.shared.u64 t, %1; cvt.u32.u64 %0, t; }"
        : "=r"(a) : "l"(p));
    return a;
}
#define LDSM4(r, addr) \
    asm volatile("ldmatrix.sync.aligned.m8n8.x4.shared.b16 {%0,%1,%2,%3}, [%4];" \
        : "=r"((r)[0]), "=r"((r)[1]), "=r"((r)[2]), "=r"((r)[3]) : "r"(addr))
#define MMA_F16(C, A, b0, b1) \
    asm volatile("mma.sync.aligned.m16n8k16.row.col.f32.f16.f16.f32 " \
        "{%0,%1,%2,%3},{%4,%5,%6,%7},{%8,%9},{%0,%1,%2,%3};" \
        : "+f"((C)[0]), "+f"((C)[1]), "+f"((C)[2]), "+f"((C)[3]) \
        : "r"((A)[0]), "r"((A)[1]), "r"((A)[2]), "r"((A)[3]), "r"(b0), "r"(b1))
#define CP_ASYNC16(dst, src) \
    asm volatile("cp.async.ca.shared.global [%0], [%1], 16;" :: "r"(dst), "l"(src))
#define CP_COMMIT() asm volatile("cp.async.commit_group;")
#define CP_WAIT_ALL() asm volatile("cp.async.wait_all;")
// NOTE: parameter names must not collide with float4 member names
#define FMA4(accv, sclr, wvec) { (accv).x += (sclr)*(wvec).x; \
                                 (accv).y += (sclr)*(wvec).y; \
                                 (accv).z += (sclr)*(wvec).z; \
                                 (accv).w += (sclr)*(wvec).w; }

__device__ __forceinline__ void split16(float v, __half& a, __half& b) {
    a = __float2half(v);
    b = __float2half(v - __half2float(a));
}

// ---------------- K1: fused projections (nodes + edges) --------------------
__global__ void k_proj(const float* __restrict__ nf,
                       const float* __restrict__ Wp,
                       const float* __restrict__ bp,
                       const float* __restrict__ ea,
                       const float* __restrict__ Wpe,
                       const float* __restrict__ bpe) {
    __shared__ float s[256];
    int tid = threadIdx.x;
    if (blockIdx.x < 1024) {
        int n0 = blockIdx.x * 4;
        s[tid] = nf[(size_t)n0 * 64 + tid];
        __syncthreads();
        int nl = tid >> 6, c = tid & 63;
        float sum = bp[c];
#pragma unroll 16
        for (int k = 0; k < 64; k++) sum += s[nl * 64 + k] * Wp[k * 64 + c];
        float v = fmaxf(sum, 0.f);
        size_t o = (size_t)(n0 + nl) * 64 + c;
        g_h[o] = v;
        __half a, b; split16(v, a, b);
        g_h1[o] = a; g_h2[o] = b;
    } else {
        int e0 = (blockIdx.x - 1024) * 2;
        if (tid < 32) s[tid] = ea[(size_t)e0 * 16 + tid];
        __syncthreads();
        int el = tid >> 7, c = tid & 127;
        float sum = bpe[c];
#pragma unroll
        for (int k = 0; k < 16; k++) sum += s[el * 16 + k] * Wpe[k * 128 + c];
        float v = fmaxf(sum, 0.f);
        size_t idx = (size_t)(e0 + el) * 128 + c;
        g_e[idx] = v;
        __half a, b; split16(v, a, b);
        g_e1[idx] = a; g_e2[idx] = b;
    }
}

// ---------------- fused weight transpose + fp16 limb split -----------------
__global__ void k_split_all(const float* __restrict__ Wnn,
                            const float* __restrict__ We1,
                            const float* __restrict__ We2) {
    __shared__ float t[32][33];
    int x = threadIdx.x, y = threadIdx.y;           // 32 x 8
    int b = blockIdx.x;
    const float* W; int K, N, sel, bx, by;
    if (b < 512)      { W = Wnn; K = 128; N = 4096; sel = 0; bx = b & 127; by = b >> 7; }
    else if (b < 544) { b -= 512; W = We1; K = 256; N = 128; sel = 1; bx = b & 3; by = b >> 2; }
    else              { b -= 544; W = We2; K = 128; N = 128; sel = 2; bx = b & 3; by = b >> 2; }
    int nb = bx * 32, kb = by * 32;
#pragma unroll
    for (int i = 0; i < 4; i++)
        t[y + 8 * i][x] = W[(size_t)(kb + y + 8 * i) * N + nb + x];
    __syncthreads();
    __half* d1 = (sel == 0) ? g_Wt1 : (sel == 1) ? g_We1T1 : g_We2T1;
    __half* d2 = (sel == 1) ? g_We1T2 : g_We2T2;
#pragma unroll
    for (int i = 0; i < 4; i++) {
        float v = t[x][y + 8 * i];
        size_t o = (size_t)(nb + y + 8 * i) * K + kb + x;
        __half a, b2; split16(v, a, b2);
        d1[o] = a;
        if (sel != 0) d2[o] = b2;
    }
}

// ---------------- K4: NNConv, fp16 single-pass mma, n-split x4 -------------
#define NC_SMEM 55808
#define OFF_BIAS 1024
#define OFF_HS   5120
#define OFF_AB   38400
extern "C" __global__ void __launch_bounds__(256, 3)
k_nnconv_mma(const int* __restrict__ eidx, const float* __restrict__ b_nn) {
    extern __shared__ char sm[];
    int* sc = (int*)sm;
    int* tcs = (int*)(sm + 512);
    float* sbias = (float*)(sm + OFF_BIAS);
    float* hs = (float*)(sm + OFF_HS);
    char* AB = sm + OFF_AB;
    const uint32_t ABu = smem_u32(AB);

    const int tid = threadIdx.x;
    const int q = blockIdx.x & 3;
    const int e0 = (blockIdx.x >> 2) * 128;
    const int ncol0 = q * 16;
    const int w = tid >> 5, lane = tid & 31;

    if (tid < 128) sc[tid] = eidx[e0 + tid];
    else           tcs[tid - 128] = eidx[N_EDGES + e0 + (tid - 128)];
    {
        int d = tid >> 2, jq = tid & 3;
        *(float4*)(sbias + d * 16 + jq * 4) =
            *(const float4*)(b_nn + d * 64 + ncol0 + jq * 4);
    }
    __syncthreads();

    {
        int l = tid >> 1, d0 = (tid & 1) * 32;
        const float* hrow = g_h + (size_t)sc[l] * 64 + d0;
        float* dst = hs + l * 65 + d0;
#pragma unroll
        for (int i = 0; i < 32; i += 4) {
            float4 v = *(const float4*)(hrow + i);
            dst[i] = v.x; dst[i + 1] = v.y; dst[i + 2] = v.z; dst[i + 3] = v.w;
        }
    }

    uint32_t a1[8][4];
    {
        const uint4* s1 = (const uint4*)(g_e1 + (size_t)e0 * 128);
#pragma unroll
        for (int r = 0; r < 2; r++) {
            __syncthreads();
#pragma unroll
            for (int it = 0; it < 4; it++) {
                int idx = it * 256 + tid;
                int row = idx >> 4, sl = idx & 15;
                *(uint4*)(AB + row * 272 + sl * 16) = s1[(64 * r + row) * 16 + sl];
            }
            __syncthreads();
            if ((w >> 2) == r) {
                uint32_t base = ABu + (uint32_t)((16 * (w & 3) + (lane & 15)) * 272 +
                                                 (lane >> 4) * 16);
#pragma unroll
                for (int kf = 0; kf < 8; kf++) LDSM4(a1[kf], base + kf * 32);
            }
        }
        __syncthreads();
    }

    {
        int row = tid >> 4, sl = tid & 15;
        CP_ASYNC16(ABu + row * 272 + sl * 16,
                   g_Wt1 + (size_t)(ncol0 + row) * 128 + sl * 8);
    }
    CP_COMMIT();

    const int gid = lane >> 2, tpair = (lane & 3) * 2;
    const int row0 = 16 * w + gid;
    const float* hvp0 = hs + row0 * 65;
    const float* hvp1 = hs + (row0 + 8) * 65;
    const uint32_t boff = (uint32_t)((lane & 7) * 272 + ((lane >> 3) & 1) * 16 +
                                     (lane >> 4) * 2176);
    float msg[2][4] = {};

    for (int d = 0; d < 64; d++) {
        CP_WAIT_ALL();
        __syncthreads();
        if (d + 1 < 64) {
            int row = tid >> 4, sl = tid & 15;
            CP_ASYNC16(ABu + ((d + 1) & 1) * 4352 + row * 272 + sl * 16,
                       g_Wt1 + (size_t)((d + 1) * 64 + ncol0 + row) * 128 + sl * 8);
            CP_COMMIT();
        }

        float C[2][4];
        const float* bptr = sbias + d * 16 + tpair;
#pragma unroll
        for (int nf = 0; nf < 2; nf++) {
            float2 bv = *(const float2*)(bptr + nf * 8);
            C[nf][0] = bv.x; C[nf][1] = bv.y;
            C[nf][2] = bv.x; C[nf][3] = bv.y;
        }
        const uint32_t bb = ABu + (d & 1) * 4352 + boff;
#pragma unroll
        for (int kf = 0; kf < 8; kf++) {
            uint32_t b[4];
            LDSM4(b, bb + kf * 32);
            MMA_F16(C[0], a1[kf], b[0], b[1]);
            MMA_F16(C[1], a1[kf], b[2], b[3]);
        }
        float hv0 = hvp0[d], hv1 = hvp1[d];
#pragma unroll
        for (int nf = 0; nf < 2; nf++) {
            msg[nf][0] = fmaf(hv0, fmaxf(C[nf][0], 0.f), msg[nf][0]);
            msg[nf][1] = fmaf(hv0, fmaxf(C[nf][1], 0.f), msg[nf][1]);
            msg[nf][2] = fmaf(hv1, fmaxf(C[nf][2], 0.f), msg[nf][2]);
            msg[nf][3] = fmaf(hv1, fmaxf(C[nf][3], 0.f), msg[nf][3]);
        }
    }

    float* d0 = g_agg + (size_t)tcs[row0] * 64 + ncol0 + tpair;
    float* d1 = g_agg + (size_t)tcs[row0 + 8] * 64 + ncol0 + tpair;
#pragma unroll
    for (int nf = 0; nf < 2; nf++) {
        atomicAdd(d0 + nf * 8,     msg[nf][0]);
        atomicAdd(d0 + nf * 8 + 1, msg[nf][1]);
        atomicAdd(d1 + nf * 8,     msg[nf][2]);
        atomicAdd(d1 + nf * 8 + 1, msg[nf][3]);
    }
}

// ---------------- K5+K6: conv + GRU, 512thr, float4 ILP --------------------
// grid 128, 32 nodes/CTA, 16 warps. shr/smm stride 68 (272B rows: 16B-aligned
// AND conflict-free for LDS.128: lanes hit banks 4*lane). h/m loaded as float4
// pairs (8 k per 2 LDS). Weight LDS warp-broadcast. Warps 0-7: phase A;
// warps 8-15 concurrently: gh. Then all: gi. Bitwise-identical accumulation.
// smem floats: Wr@0(4096) Wih@4096(12288) Whh@16384(12288)
//   shr@28672(2176) smm@30848(2176) sgi@33024(6272,str196) sgh@39296(6272)
//   total 45568 floats = 182272 B
#define CG_SMEM 182272
__global__ void __launch_bounds__(512, 1)
k_conv_gru(const float* __restrict__ Wr,  const float* __restrict__ bc,
           const float* __restrict__ wih, const float* __restrict__ whh,
           const float* __restrict__ bih, const float* __restrict__ bhh,
           float* __restrict__ outp) {
    extern __shared__ float s[];
    float* sWr  = s;
    float* sWih = s + 4096;
    float* sWhh = s + 16384;
    float* shr  = s + 28672;   // [n*68 + k]
    float* smm  = s + 30848;   // [n*68 + k]
    float* sgi  = s + 33024;   // [n*196 + c]
    float* sgh  = s + 39296;

    const int tid = threadIdx.x;
    const int n0 = blockIdx.x * 32;
    const int w = tid >> 5, lane = tid & 31;   // lane = node

    // weights -> smem (512 threads)
    for (int i = tid; i < 1024; i += 512)
        ((float4*)sWr)[i] = ((const float4*)Wr)[i];
    for (int i = tid; i < 3072; i += 512) {
        ((float4*)sWih)[i] = ((const float4*)wih)[i];
        ((float4*)sWhh)[i] = ((const float4*)whh)[i];
    }
    // h rows -> shr (stride 68, float4 stores); threads 0-255 only
    if (tid < 256) {
        int n = tid >> 3, c8 = (tid & 7) * 8;
        float4 va = *(const float4*)(g_h + (size_t)(n0 + n) * 64 + c8);
        float4 vb = *(const float4*)(g_h + (size_t)(n0 + n) * 64 + c8 + 4);
        float* dst = shr + n * 68 + c8;
        *(float4*)dst = va;
        *(float4*)(dst + 4) = vb;
    }
    __syncthreads();

    if (w < 8) {
        // ---- phase A: m = relu(agg + h@Wr + bc); warp w -> cols 8w..8w+7
        const int cb = w * 8;
        float* aggp = g_agg + (size_t)(n0 + lane) * 64 + cb;
        float4 acc0 = *(const float4*)aggp;
        float4 acc1 = *(const float4*)(aggp + 4);
        *(float4*)aggp = make_float4(0.f, 0.f, 0.f, 0.f);
        *(float4*)(aggp + 4) = make_float4(0.f, 0.f, 0.f, 0.f);
        float4 bc0 = *(const float4*)(bc + cb);
        float4 bc1 = *(const float4*)(bc + cb + 4);
        acc0.x += bc0.x; acc0.y += bc0.y; acc0.z += bc0.z; acc0.w += bc0.w;
        acc1.x += bc1.x; acc1.y += bc1.y; acc1.z += bc1.z; acc1.w += bc1.w;
        const float* hp = shr + lane * 68;
#pragma unroll
        for (int k8 = 0; k8 < 64; k8 += 8) {
            float4 hA = *(const float4*)(hp + k8);
            float4 hB = *(const float4*)(hp + k8 + 4);
            float hv[8] = {hA.x, hA.y, hA.z, hA.w, hB.x, hB.y, hB.z, hB.w};
#pragma unroll
            for (int j = 0; j < 8; j++) {
                int k = k8 + j;
                float4 wv0 = *(const float4*)(sWr + k * 64 + cb);       // bcast
                float4 wv1 = *(const float4*)(sWr + k * 64 + cb + 4);   // bcast
                FMA4(acc0, hv[j], wv0);
                FMA4(acc1, hv[j], wv1);
            }
        }
        float* mp = smm + lane * 68 + cb;
        float4 r0 = make_float4(fmaxf(acc0.x, 0.f), fmaxf(acc0.y, 0.f),
                                fmaxf(acc0.z, 0.f), fmaxf(acc0.w, 0.f));
        float4 r1 = make_float4(fmaxf(acc1.x, 0.f), fmaxf(acc1.y, 0.f),
                                fmaxf(acc1.z, 0.f), fmaxf(acc1.w, 0.f));
        *(float4*)mp = r0;
        *(float4*)(mp + 4) = r1;
    } else {
        // ---- phase gh (concurrent): gh = h@whh + bhh; warp (w-8) -> 24 cols
        const int cb = (w - 8) * 24;
        const float* src = shr + lane * 68;
        float* dst = sgh + lane * 196 + cb;
        float4 acc[6];
#pragma unroll
        for (int j = 0; j < 6; j++)
            acc[j] = *(const float4*)(bhh + cb + j * 4);
#pragma unroll
        for (int k8 = 0; k8 < 64; k8 += 8) {
            float4 hA = *(const float4*)(src + k8);
            float4 hB = *(const float4*)(src + k8 + 4);
            float hv[8] = {hA.x, hA.y, hA.z, hA.w, hB.x, hB.y, hB.z, hB.w};
#pragma unroll
            for (int j8 = 0; j8 < 8; j8++) {
                const float* wr = sWhh + (k8 + j8) * 192 + cb;
#pragma unroll
                for (int j = 0; j < 6; j++) {
                    float4 wv = *(const float4*)(wr + j * 4);   // bcast
                    FMA4(acc[j], hv[j8], wv);
                }
            }
        }
#pragma unroll
        for (int j = 0; j < 6; j++)
            *(float4*)(dst + j * 4) = acc[j];
    }
    __syncthreads();

    // ---- phase gi: all 16 warps: gi = m@wih + bih; warp w -> 12 cols
    {
        const int cb = w * 12;
        const float* src = smm + lane * 68;
        float* dst = sgi + lane * 196 + cb;
        float4 acc[3];
#pragma unroll
        for (int j = 0; j < 3; j++)
            acc[j] = *(const float4*)(bih + cb + j * 4);
#pragma unroll
        for (int k8 = 0; k8 < 64; k8 += 8) {
            float4 mA = *(const float4*)(src + k8);
            float4 mB = *(const float4*)(src + k8 + 4);
            float mv[8] = {mA.x, mA.y, mA.z, mA.w, mB.x, mB.y, mB.z, mB.w};
#pragma unroll
            for (int j8 = 0; j8 < 8; j8++) {
                const float* wr = sWih + (k8 + j8) * 192 + cb;
#pragma unroll
                for (int j = 0; j < 3; j++) {
                    float4 wv = *(const float4*)(wr + j * 4);   // bcast
                    FMA4(acc[j], mv[j8], wv);
                }
            }
        }
#pragma unroll
        for (int j = 0; j < 3; j++)
            *(float4*)(dst + j * 4) = acc[j];
    }
    __syncthreads();

    // ---- gates ----
    for (int i = tid; i < 2048; i += 512) {
        int n = i >> 6, c = i & 63;
        const float* gi = sgi + n * 196;
        const float* gh = sgh + n * 196;
        float r = 1.f / (1.f + expf(-(gi[c] + gh[c])));
        float z = 1.f / (1.f + expf(-(gi[64 + c] + gh[64 + c])));
        float nc = tanhf(gi[128 + c] + r * gh[128 + c]);
        float v = (1.f - z) * nc + z * shr[n * 68 + c];
        size_t o = (size_t)(n0 + n) * 64 + c;
        g_h[o] = v;
        if (outp) outp[o] = v;
        __half a, b; split16(v, a, b);
        g_h1[o] = a; g_h2[o] = b;
    }
}

// ---------------- K7: edge-update MLP, 32-edge CTAs, occ 2 -----------------
#define EU_SMEM   104960
#define EU_OFF_A  1536
#define EU_A_PL   16896
#define EU_OFF_B  35328
#define EU_T_PL   8704
#define EU_B2_PL  34816
extern "C" __global__ void __launch_bounds__(256, 2)
k_edgeup_tc(const int* __restrict__ eidx,
            const float* __restrict__ b1, const float* __restrict__ b2,
            float* __restrict__ oute) {
    extern __shared__ char sm[];
    const uint32_t sbase = smem_u32(sm);
    int* sc = (int*)sm;
    int* tcs = (int*)(sm + 128);
    float* b1s = (float*)(sm + 512);
    float* b2s = (float*)(sm + 1024);

    const int tid = threadIdx.x;
    const int e0 = blockIdx.x * 32;
    const int w = tid >> 5, lane = tid & 31;

    if (tid < 32)      sc[tid] = eidx[e0 + tid];
    else if (tid < 64) tcs[tid - 32] = eidx[N_EDGES + e0 + (tid - 32)];
    else if (tid < 192) b1s[tid - 64] = b1[tid - 64];
    else               b2s[tid - 192] = b2[tid - 192];
    if (tid < 64) b2s[64 + tid] = b2[64 + tid];

    for (int i = tid; i < 4096; i += 256) {
        int n = i >> 5, c = i & 31;
        CP_ASYNC16(sbase + EU_OFF_B + n * 528 + c * 16,
                   g_We1T1 + (size_t)n * 256 + c * 8);
    }
    CP_COMMIT();
    __syncthreads();

    for (int i = tid; i < 512; i += 256) {
        int s2 = i >> 8, j = i & 255;
        int l = j >> 3, c = (j & 7) * 8;
        int nrow = s2 ? tcs[l] : sc[l];
        const uint4* s1 = (const uint4*)(g_h1 + (size_t)nrow * 64 + c);
        const uint4* s2p = (const uint4*)(g_h2 + (size_t)nrow * 64 + c);
        char* dst = sm + EU_OFF_A + l * 528 + s2 * 128 + c * 2;
        *(uint4*)dst = *s1;
        *(uint4*)(dst + EU_A_PL) = *s2p;
    }
    for (int i = tid; i < 512; i += 256) {
        int l = i >> 4, c = (i & 15) * 8;
        const uint4* s1 = (const uint4*)(g_e1 + (size_t)(e0 + l) * 128 + c);
        const uint4* s2p = (const uint4*)(g_e2 + (size_t)(e0 + l) * 128 + c);
        char* dst = sm + EU_OFF_A + l * 528 + 256 + c * 2;
        *(uint4*)dst = *s1;
        *(uint4*)(dst + EU_A_PL) = *s2p;
    }
    CP_WAIT_ALL();
    __syncthreads();

    const int mf = w & 1, nh = w >> 1;
    const int nbase = nh * 32;
    const int gid = lane >> 2, tpair = (lane & 3) * 2;
    const uint32_t aoff = (uint32_t)((16 * mf + (lane & 15)) * 528 + (lane >> 4) * 16);
    const uint32_t boff = (uint32_t)((nbase + (lane >> 4) * 8 + (lane & 7)) * 528 +
                                     ((lane >> 3) & 1) * 16);

    float C[4][4];
#pragma unroll
    for (int nf = 0; nf < 4; nf++) {
        float2 bv = *(const float2*)(b1s + nbase + nf * 8 + tpair);
        C[nf][0] = bv.x; C[nf][1] = bv.y;
        C[nf][2] = bv.x; C[nf][3] = bv.y;
    }

#pragma unroll
    for (int kf = 0; kf < 16; kf++) {
        uint32_t fa1[4], fa2[4];
        LDSM4(fa1, sbase + EU_OFF_A + aoff + kf * 32);
        LDSM4(fa2, sbase + EU_OFF_A + EU_A_PL + aoff + kf * 32);
#pragma unroll
        for (int p = 0; p < 2; p++) {
            uint32_t b[4];
            LDSM4(b, sbase + EU_OFF_B + boff + p * 8448 + kf * 32);
            MMA_F16(C[2 * p],     fa1, b[0], b[1]);
            MMA_F16(C[2 * p],     fa2, b[0], b[1]);
            MMA_F16(C[2 * p + 1], fa1, b[2], b[3]);
            MMA_F16(C[2 * p + 1], fa2, b[2], b[3]);
        }
    }
    __syncthreads();

    for (int i = tid; i < 4096; i += 256) {
        int n = i >> 5, c = i & 31;
        CP_ASYNC16(sbase + EU_OFF_B + n * 528 + c * 16,
                   g_We1T2 + (size_t)n * 256 + c * 8);
    }
    CP_COMMIT();
    CP_WAIT_ALL();
    __syncthreads();

#pragma unroll
    for (int kf = 0; kf < 16; kf++) {
        uint32_t fa1[4];
        LDSM4(fa1, sbase + EU_OFF_A + aoff + kf * 32);
#pragma unroll
        for (int p = 0; p < 2; p++) {
            uint32_t b[4];
            LDSM4(b, sbase + EU_OFF_B + boff + p * 8448 + kf * 32);
            MMA_F16(C[2 * p],     fa1, b[0], b[1]);
            MMA_F16(C[2 * p + 1], fa1, b[2], b[3]);
        }
    }
    __syncthreads();

    for (int i = tid; i < 4096; i += 256) {
        int p = i >> 11, n = (i >> 4) & 127, c = i & 15;
        const __half* src = (p ? g_We2T2 : g_We2T1) + (size_t)n * 128 + c * 8;
        CP_ASYNC16(sbase + EU_OFF_B + p * EU_B2_PL + n * 272 + c * 16, src);
    }
    CP_COMMIT();

    {
        int r0 = 16 * mf + gid;
#pragma unroll
        for (int nf = 0; nf < 4; nf++) {
            int col = nbase + nf * 8 + tpair;
#pragma unroll
            for (int half = 0; half < 2; half++) {
                int r = r0 + half * 8;
                float v0 = fmaxf(C[nf][2 * half], 0.f);
                float v1 = fmaxf(C[nf][2 * half + 1], 0.f);
                __half a0, c0, a1_, c1;
                split16(v0, a0, c0);
                split16(v1, a1_, c1);
                char* base = sm + EU_OFF_A + r * 272 + col * 2;
                *(__half2*)base = __halves2half2(a0, a1_);
                *(__half2*)(base + EU_T_PL) = __halves2half2(c0, c1);
            }
        }
    }
    CP_WAIT_ALL();
    __syncthreads();

    const uint32_t toff = (uint32_t)((16 * mf + (lane & 15)) * 272 + (lane >> 4) * 16);
    const uint32_t b2off = (uint32_t)((nbase + (lane & 7)) * 272 +
                                      ((lane >> 3) & 1) * 16 +
                                      (lane >> 4) * EU_B2_PL);
    float C2[4][4];
#pragma unroll
    for (int nf = 0; nf < 4; nf++) {
        float2 bv = *(const float2*)(b2s + nbase + nf * 8 + tpair);
        C2[nf][0] = bv.x; C2[nf][1] = bv.y;
        C2[nf][2] = bv.x; C2[nf][3] = bv.y;
    }
#pragma unroll
    for (int kf = 0; kf < 8; kf++) {
        uint32_t fa1[4], fa2[4];
        LDSM4(fa1, sbase + EU_OFF_A + toff + kf * 32);
        LDSM4(fa2, sbase + EU_OFF_A + EU_T_PL + toff + kf * 32);
#pragma unroll
        for (int nf = 0; nf < 4; nf++) {
            uint32_t b[4];
            LDSM4(b, sbase + EU_OFF_B + b2off + nf * 2176 + kf * 32);
            MMA_F16(C2[nf], fa1, b[0], b[1]);
            MMA_F16(C2[nf], fa2, b[0], b[1]);
            MMA_F16(C2[nf], fa1, b[2], b[3]);
        }
    }

    {
        int r0 = 16 * mf + gid;
#pragma unroll
        for (int nf = 0; nf < 4; nf++) {
            int col = nbase + nf * 8 + tpair;
#pragma unroll
            for (int half = 0; half < 2; half++) {
                int r = r0 + half * 8;
                size_t o = (size_t)(e0 + r) * 128 + col;
                float v0 = fmaxf(C2[nf][2 * half], 0.f);
                float v1 = fmaxf(C2[nf][2 * half + 1], 0.f);
                g_e[o] = v0; g_e[o + 1] = v1;
                if (oute) { oute[o] = v0; oute[o + 1] = v1; }
                __half a0, c0, a1_, c1;
                split16(v0, a0, c0);
                split16(v1, a1_, c1);
                *(__half2*)(g_e1 + o) = __halves2half2(a0, a1_);
                *(__half2*)(g_e2 + o) = __halves2half2(c0, c1);
            }
        }
    }
}

// ---------------- launcher -------------------------------------------------
extern "C" void kernel_launch(void* const* d_in, const int* in_sizes, int n_in,
                              void* d_out, int out_size) {
    const float* nf   = (const float*)d_in[0];
    const float* ea   = (const float*)d_in[1];
    const int*   eidx = (const int*)  d_in[2];
    const float* Wp   = (const float*)d_in[3];
    const float* bp   = (const float*)d_in[4];
    const float* Wpe  = (const float*)d_in[5];
    const float* bpe  = (const float*)d_in[6];
    const float* Wnn  = (const float*)d_in[7];
    const float* bnn  = (const float*)d_in[8];
    const float* Wr   = (const float*)d_in[9];
    const float* bc   = (const float*)d_in[10];
    const float* wih  = (const float*)d_in[11];
    const float* whh  = (const float*)d_in[12];
    const float* bih  = (const float*)d_in[13];
    const float* bhh  = (const float*)d_in[14];
    const float* We1  = (const float*)d_in[15];
    const float* be1  = (const float*)d_in[16];
    const float* We2  = (const float*)d_in[17];
    const float* be2  = (const float*)d_in[18];

    float* out_h = (float*)d_out;
    float* out_e = (float*)d_out + (size_t)N_NODES * DIM;

    cudaFuncSetAttribute(k_nnconv_mma, cudaFuncAttributeMaxDynamicSharedMemorySize, NC_SMEM);
    cudaFuncSetAttribute(k_edgeup_tc, cudaFuncAttributeMaxDynamicSharedMemorySize, EU_SMEM);
    cudaFuncSetAttribute(k_conv_gru, cudaFuncAttributeMaxDynamicSharedMemorySize, CG_SMEM);

    k_split_all<<<560, dim3(32, 8)>>>(Wnn, We1, We2);
    k_proj<<<1024 + N_EDGES / 2, 256>>>(nf, Wp, bp, ea, Wpe, bpe);

    for (int step = 0; step < NUM_STEPS; step++) {
        bool last = (step == NUM_STEPS - 1);
        k_nnconv_mma<<<(N_EDGES / 128) * 4, 256, NC_SMEM>>>(eidx, bnn);
        k_conv_gru<<<N_NODES / 32, 512, CG_SMEM>>>(Wr, bc, wih, whh, bih, bhh,
                                                   last ? out_h : (float*)nullptr);
        k_edgeup_tc<<<N_EDGES / 32, 256, EU_SMEM>>>(eidx, be1, be2,
                                                    last ? out_e : (float*)nullptr);
    }
}

// round 13
// speedup vs baseline: 1.0460x; 1.0323x over previous
#include <cuda_runtime.h>
#include <cuda_fp16.h>
#include <math.h>
#include <stdint.h>

#define N_NODES 4096
#define N_EDGES 32768
#define DIM 64
#define EHID 128
#define NUM_STEPS 3

// ---------------- scratch (device globals; zero-initialized) ----------------
__device__ float g_h[N_NODES * DIM];
__device__ float g_e[N_EDGES * EHID];
__device__ float g_agg[N_NODES * DIM];    // invariant: zero at kernel_launch entry
__device__ __half g_h1[N_NODES * DIM];
__device__ __half g_h2[N_NODES * DIM];
__device__ __half g_e1[N_EDGES * EHID];
__device__ __half g_e2[N_EDGES * EHID];
__device__ __half g_Wt1[4096 * 128];      // W_nn^T [n][k] limb1
__device__ __half g_We1T1[128 * 256];
__device__ __half g_We1T2[128 * 256];
__device__ __half g_We2T1[128 * 128];
__device__ __half g_We2T2[128 * 128];
__device__ __half g_WrT1[64 * 64],   g_WrT2[64 * 64];     // W_root^T limbs
__device__ __half g_WihT1[192 * 64], g_WihT2[192 * 64];   // w_ih^T limbs
__device__ __half g_WhhT1[192 * 64], g_WhhT2[192 * 64];   // w_hh^T limbs

// ---------------- helpers ---------------------------------------------------
__device__ __forceinline__ uint32_t smem_u32(const void* p) {
    uint32_t a;
    asm("{ .reg .u64 t; cvta.to.shared.u64 t, %1; cvt.u32.u64 %0, t; }"
        : "=r"(a) : "l"(p));
    return a;
}
#define LDSM4(r, addr) \
    asm volatile("ldmatrix.sync.aligned.m8n8.x4.shared.b16 {%0,%1,%2,%3}, [%4];" \
        : "=r"((r)[0]), "=r"((r)[1]), "=r"((r)[2]), "=r"((r)[3]) : "r"(addr))
#define MMA_F16(C, A, b0, b1) \
    asm volatile("mma.sync.aligned.m16n8k16.row.col.f32.f16.f16.f32 " \
        "{%0,%1,%2,%3},{%4,%5,%6,%7},{%8,%9},{%0,%1,%2,%3};" \
        : "+f"((C)[0]), "+f"((C)[1]), "+f"((C)[2]), "+f"((C)[3]) \
        : "r"((A)[0]), "r"((A)[1]), "r"((A)[2]), "r"((A)[3]), "r"(b0), "r"(b1))
#define CP_ASYNC16(dst, src) \
    asm volatile("cp.async.ca.shared.global [%0], [%1], 16;" :: "r"(dst), "l"(src))
#define CP_COMMIT() asm volatile("cp.async.commit_group;")
#define CP_WAIT_ALL() asm volatile("cp.async.wait_all;")
#define CP_WAIT_GROUP(n) asm volatile("cp.async.wait_group %0;" :: "n"(n))

__device__ __forceinline__ void split16(float v, __half& a, __half& b) {
    a = __float2half(v);
    b = __float2half(v - __half2float(a));
}

// ---------------- K1: fused projections (nodes + edges) --------------------
__global__ void k_proj(const float* __restrict__ nf,
                       const float* __restrict__ Wp,
                       const float* __restrict__ bp,
                       const float* __restrict__ ea,
                       const float* __restrict__ Wpe,
                       const float* __restrict__ bpe) {
    __shared__ float s[256];
    int tid = threadIdx.x;
    if (blockIdx.x < 1024) {
        int n0 = blockIdx.x * 4;
        s[tid] = nf[(size_t)n0 * 64 + tid];
        __syncthreads();
        int nl = tid >> 6, c = tid & 63;
        float sum = bp[c];
#pragma unroll 16
        for (int k = 0; k < 64; k++) sum += s[nl * 64 + k] * Wp[k * 64 + c];
        float v = fmaxf(sum, 0.f);
        size_t o = (size_t)(n0 + nl) * 64 + c;
        g_h[o] = v;
        __half a, b; split16(v, a, b);
        g_h1[o] = a; g_h2[o] = b;
    } else {
        int e0 = (blockIdx.x - 1024) * 2;
        if (tid < 32) s[tid] = ea[(size_t)e0 * 16 + tid];
        __syncthreads();
        int el = tid >> 7, c = tid & 127;
        float sum = bpe[c];
#pragma unroll
        for (int k = 0; k < 16; k++) sum += s[el * 16 + k] * Wpe[k * 128 + c];
        float v = fmaxf(sum, 0.f);
        size_t idx = (size_t)(e0 + el) * 128 + c;
        g_e[idx] = v;
        __half a, b; split16(v, a, b);
        g_e1[idx] = a; g_e2[idx] = b;
    }
}

// ---------------- fused weight transpose + fp16 limb split -----------------
__global__ void k_split_all(const float* __restrict__ Wnn,
                            const float* __restrict__ We1,
                            const float* __restrict__ We2,
                            const float* __restrict__ Wr,
                            const float* __restrict__ wih,
                            const float* __restrict__ whh) {
    __shared__ float t[32][33];
    int x = threadIdx.x, y = threadIdx.y;           // 32 x 8
    int b = blockIdx.x;
    const float* W; int K, N, sel, bx, by;
    if (b < 512)      { W = Wnn; K = 128; N = 4096; sel = 0; bx = b & 127; by = b >> 7; }
    else if (b < 544) { b -= 512; W = We1; K = 256; N = 128; sel = 1; bx = b & 3; by = b >> 2; }
    else if (b < 560) { b -= 544; W = We2; K = 128; N = 128; sel = 2; bx = b & 3; by = b >> 2; }
    else if (b < 564) { b -= 560; W = Wr;  K = 64;  N = 64;  sel = 3; bx = b & 1; by = b >> 1; }
    else if (b < 576) { b -= 564; W = wih; K = 64;  N = 192; sel = 4; bx = b % 6; by = b / 6; }
    else              { b -= 576; W = whh; K = 64;  N = 192; sel = 5; bx = b % 6; by = b / 6; }
    int nb = bx * 32, kb = by * 32;
#pragma unroll
    for (int i = 0; i < 4; i++)
        t[y + 8 * i][x] = W[(size_t)(kb + y + 8 * i) * N + nb + x];
    __syncthreads();
    __half *d1, *d2 = nullptr;
    switch (sel) {
        case 0: d1 = g_Wt1; break;
        case 1: d1 = g_We1T1; d2 = g_We1T2; break;
        case 2: d1 = g_We2T1; d2 = g_We2T2; break;
        case 3: d1 = g_WrT1;  d2 = g_WrT2;  break;
        case 4: d1 = g_WihT1; d2 = g_WihT2; break;
        default: d1 = g_WhhT1; d2 = g_WhhT2; break;
    }
#pragma unroll
    for (int i = 0; i < 4; i++) {
        float v = t[x][y + 8 * i];
        size_t o = (size_t)(nb + y + 8 * i) * K + kb + x;
        __half a, b2; split16(v, a, b2);
        d1[o] = a;
        if (d2) d2[o] = b2;
    }
}

// ---------------- K4: NNConv, fp16 single-pass mma, n-split x4 -------------
#define NC_SMEM 55808
#define OFF_BIAS 1024
#define OFF_HS   5120
#define OFF_AB   38400
extern "C" __global__ void __launch_bounds__(256, 3)
k_nnconv_mma(const int* __restrict__ eidx, const float* __restrict__ b_nn) {
    extern __shared__ char sm[];
    int* sc = (int*)sm;
    int* tcs = (int*)(sm + 512);
    float* sbias = (float*)(sm + OFF_BIAS);
    float* hs = (float*)(sm + OFF_HS);
    char* AB = sm + OFF_AB;
    const uint32_t ABu = smem_u32(AB);

    const int tid = threadIdx.x;
    const int q = blockIdx.x & 3;
    const int e0 = (blockIdx.x >> 2) * 128;
    const int ncol0 = q * 16;
    const int w = tid >> 5, lane = tid & 31;

    if (tid < 128) sc[tid] = eidx[e0 + tid];
    else           tcs[tid - 128] = eidx[N_EDGES + e0 + (tid - 128)];
    {
        int d = tid >> 2, jq = tid & 3;
        *(float4*)(sbias + d * 16 + jq * 4) =
            *(const float4*)(b_nn + d * 64 + ncol0 + jq * 4);
    }
    __syncthreads();

    {
        int l = tid >> 1, d0 = (tid & 1) * 32;
        const float* hrow = g_h + (size_t)sc[l] * 64 + d0;
        float* dst = hs + l * 65 + d0;
#pragma unroll
        for (int i = 0; i < 32; i += 4) {
            float4 v = *(const float4*)(hrow + i);
            dst[i] = v.x; dst[i + 1] = v.y; dst[i + 2] = v.z; dst[i + 3] = v.w;
        }
    }

    uint32_t a1[8][4];
    {
        const uint4* s1 = (const uint4*)(g_e1 + (size_t)e0 * 128);
#pragma unroll
        for (int r = 0; r < 2; r++) {
            __syncthreads();
#pragma unroll
            for (int it = 0; it < 4; it++) {
                int idx = it * 256 + tid;
                int row = idx >> 4, sl = idx & 15;
                *(uint4*)(AB + row * 272 + sl * 16) = s1[(64 * r + row) * 16 + sl];
            }
            __syncthreads();
            if ((w >> 2) == r) {
                uint32_t base = ABu + (uint32_t)((16 * (w & 3) + (lane & 15)) * 272 +
                                                 (lane >> 4) * 16);
#pragma unroll
                for (int kf = 0; kf < 8; kf++) LDSM4(a1[kf], base + kf * 32);
            }
        }
        __syncthreads();
    }

    {
        int row = tid >> 4, sl = tid & 15;
        CP_ASYNC16(ABu + row * 272 + sl * 16,
                   g_Wt1 + (size_t)(ncol0 + row) * 128 + sl * 8);
    }
    CP_COMMIT();

    const int gid = lane >> 2, tpair = (lane & 3) * 2;
    const int row0 = 16 * w + gid;
    const float* hvp0 = hs + row0 * 65;
    const float* hvp1 = hs + (row0 + 8) * 65;
    const uint32_t boff = (uint32_t)((lane & 7) * 272 + ((lane >> 3) & 1) * 16 +
                                     (lane >> 4) * 2176);
    float msg[2][4] = {};

    for (int d = 0; d < 64; d++) {
        CP_WAIT_ALL();
        __syncthreads();
        if (d + 1 < 64) {
            int row = tid >> 4, sl = tid & 15;
            CP_ASYNC16(ABu + ((d + 1) & 1) * 4352 + row * 272 + sl * 16,
                       g_Wt1 + (size_t)((d + 1) * 64 + ncol0 + row) * 128 + sl * 8);
            CP_COMMIT();
        }

        float C[2][4];
        const float* bptr = sbias + d * 16 + tpair;
#pragma unroll
        for (int nf = 0; nf < 2; nf++) {
            float2 bv = *(const float2*)(bptr + nf * 8);
            C[nf][0] = bv.x; C[nf][1] = bv.y;
            C[nf][2] = bv.x; C[nf][3] = bv.y;
        }
        const uint32_t bb = ABu + (d & 1) * 4352 + boff;
#pragma unroll
        for (int kf = 0; kf < 8; kf++) {
            uint32_t b[4];
            LDSM4(b, bb + kf * 32);
            MMA_F16(C[0], a1[kf], b[0], b[1]);
            MMA_F16(C[1], a1[kf], b[2], b[3]);
        }
        float hv0 = hvp0[d], hv1 = hvp1[d];
#pragma unroll
        for (int nf = 0; nf < 2; nf++) {
            msg[nf][0] = fmaf(hv0, fmaxf(C[nf][0], 0.f), msg[nf][0]);
            msg[nf][1] = fmaf(hv0, fmaxf(C[nf][1], 0.f), msg[nf][1]);
            msg[nf][2] = fmaf(hv1, fmaxf(C[nf][2], 0.f), msg[nf][2]);
            msg[nf][3] = fmaf(hv1, fmaxf(C[nf][3], 0.f), msg[nf][3]);
        }
    }

    float* d0 = g_agg + (size_t)tcs[row0] * 64 + ncol0 + tpair;
    float* d1 = g_agg + (size_t)tcs[row0 + 8] * 64 + ncol0 + tpair;
#pragma unroll
    for (int nf = 0; nf < 2; nf++) {
        atomicAdd(d0 + nf * 8,     msg[nf][0]);
        atomicAdd(d0 + nf * 8 + 1, msg[nf][1]);
        atomicAdd(d1 + nf * 8,     msg[nf][2]);
        atomicAdd(d1 + nf * 8 + 1, msg[nf][3]);
    }
}

// ---------------- K5+K6: conv + GRU on tensor cores ------------------------
// grid 128 x 256thr, 32 nodes/CTA. Exact 3-pass fp16 limb MMA (a1V1+a2V1+a1V2).
// Phase 1: m = relu(agg + h@WrT + bc)  (C seeded from agg+bias; agg re-zeroed)
// Phase 2: gi = m@wihT + bih, gh = h@whhT + bhh  (N=384 combined)
// Gates fp32 as before. A/B tiles: K=64 -> 144B row stride, LDSM addressing.
// smem (bytes): shr f32 @0 (8704, stride 68 floats)
//   A: h1@8704 h2@13312 m1@17920 m2@22528 (4608 each)
//   B: Wr@27136 (2x9216) wih@45568 (2x27648) whh@100864 (2x27648)
//   sgi@156160 (25088, stride 196 floats) sgh@181248 -> total 206336
#define CG_SMEM  206336
#define CG_SHR   0
#define CG_AH1   8704
#define CG_AH2   13312
#define CG_AM1   17920
#define CG_AM2   22528
#define CG_BWR   27136
#define CG_BWIH  45568
#define CG_BWHH  100864
#define CG_SGI   156160
#define CG_SGH   181248
__global__ void __launch_bounds__(256, 1)
k_conv_gru_tc(const float* __restrict__ bc,
              const float* __restrict__ bih, const float* __restrict__ bhh,
              float* __restrict__ outp) {
    extern __shared__ char sm[];
    const uint32_t sb = smem_u32(sm);
    float* shr = (float*)(sm + CG_SHR);
    float* sgi = (float*)(sm + CG_SGI);
    float* sgh = (float*)(sm + CG_SGH);

    const int tid = threadIdx.x;
    const int n0 = blockIdx.x * 32;
    const int w = tid >> 5, lane = tid & 31;
    const int gid = lane >> 2, tpair = (lane & 3) * 2;

    // ---- group 0: Wr B-planes + A h-limb planes ----
    for (int i = tid; i < 1024; i += 256) {           // Wr: 64r x 8c x 2pl
        int pl = i >> 9, n = (i >> 3) & 63, c = i & 7;
        CP_ASYNC16(sb + CG_BWR + pl * 9216 + n * 144 + c * 16,
                   (pl ? g_WrT2 : g_WrT1) + (size_t)n * 64 + c * 8);
    }
    for (int i = tid; i < 512; i += 256) {            // h limbs: 32r x 8c x 2pl
        int pl = i >> 8, n = (i >> 3) & 31, c = i & 7;
        CP_ASYNC16(sb + (pl ? CG_AH2 : CG_AH1) + n * 144 + c * 16,
                   (pl ? g_h2 : g_h1) + (size_t)(n0 + n) * 64 + c * 8);
    }
    CP_COMMIT();
    // ---- group 1: wih + whh B-planes ----
    for (int i = tid; i < 6144; i += 256) {           // 2 x (192r x 8c x 2pl)
        int wsel = i / 3072, j = i % 3072;
        int pl = j / 1536, r = j % 1536;
        int n = r >> 3, c = r & 7;
        const __half* src = (wsel ? (pl ? g_WhhT2 : g_WhhT1)
                                  : (pl ? g_WihT2 : g_WihT1)) + (size_t)n * 64 + c * 8;
        CP_ASYNC16(sb + (wsel ? CG_BWHH : CG_BWIH) + pl * 27648 + n * 144 + c * 16, src);
    }
    CP_COMMIT();
    // shr fp32 (regular loads)
    {
        int n = tid >> 3, c8 = (tid & 7) * 8;
        float4 va = *(const float4*)(g_h + (size_t)(n0 + n) * 64 + c8);
        float4 vb = *(const float4*)(g_h + (size_t)(n0 + n) * 64 + c8 + 4);
        float* dst = shr + n * 68 + c8;
        *(float4*)dst = va;
        *(float4*)(dst + 4) = vb;
    }
    CP_WAIT_GROUP(1);   // group 0 complete
    __syncthreads();

    const uint32_t aoff = (uint32_t)((16 * (w & 1) + (lane & 15)) * 144 +
                                     (lane >> 4) * 16);

    // ---- phase 1: conv. warp = (mf = w&1, nh = w>>1); cols nh*16..+15 ----
    {
        const int mf = w & 1, nh = w >> 1;
        const int r0 = 16 * mf + gid, r1 = r0 + 8;
        float C[2][4];
#pragma unroll
        for (int g = 0; g < 2; g++) {
            int col = nh * 16 + g * 8 + tpair;
            float2 bv = *(const float2*)(bc + col);
            float* a0p = g_agg + (size_t)(n0 + r0) * 64 + col;
            float* a1p = g_agg + (size_t)(n0 + r1) * 64 + col;
            float2 a0 = *(float2*)a0p;
            float2 a1v = *(float2*)a1p;
            *(float2*)a0p = make_float2(0.f, 0.f);
            *(float2*)a1p = make_float2(0.f, 0.f);
            C[g][0] = bv.x + a0.x;  C[g][1] = bv.y + a0.y;
            C[g][2] = bv.x + a1v.x; C[g][3] = bv.y + a1v.y;
        }
        const uint32_t bo = sb + CG_BWR +
            (uint32_t)((nh * 16 + (lane >> 4) * 8 + (lane & 7)) * 144 +
                       ((lane >> 3) & 1) * 16);
#pragma unroll
        for (int kf = 0; kf < 4; kf++) {
            uint32_t fa1[4], fa2[4], b1[4], b2[4];
            LDSM4(fa1, sb + CG_AH1 + aoff + kf * 32);
            LDSM4(fa2, sb + CG_AH2 + aoff + kf * 32);
            LDSM4(b1, bo + kf * 32);
            MMA_F16(C[0], fa1, b1[0], b1[1]);
            MMA_F16(C[1], fa1, b1[2], b1[3]);
            MMA_F16(C[0], fa2, b1[0], b1[1]);
            MMA_F16(C[1], fa2, b1[2], b1[3]);
            LDSM4(b2, bo + 9216 + kf * 32);
            MMA_F16(C[0], fa1, b2[0], b2[1]);
            MMA_F16(C[1], fa1, b2[2], b2[3]);
        }
        // relu + limb split -> m planes
#pragma unroll
        for (int g = 0; g < 2; g++) {
            int col = nh * 16 + g * 8 + tpair;
#pragma unroll
            for (int half = 0; half < 2; half++) {
                int r = (half ? r1 : r0);
                float v0 = fmaxf(C[g][2 * half], 0.f);
                float v1 = fmaxf(C[g][2 * half + 1], 0.f);
                __half a0, c0, a1h, c1;
                split16(v0, a0, c0);
                split16(v1, a1h, c1);
                *(__half2*)(sm + CG_AM1 + r * 144 + col * 2) = __halves2half2(a0, a1h);
                *(__half2*)(sm + CG_AM2 + r * 144 + col * 2) = __halves2half2(c0, c1);
            }
        }
    }
    CP_WAIT_GROUP(0);
    __syncthreads();

    // ---- phase 2: warp = (mf = w&1, cg = w>>1). cg0,1 -> gi; cg2,3 -> gh ----
    {
        const int mf = w & 1, cg = w >> 1;
        const int isGh = cg >> 1;
        const int cbase = (cg & 1) * 96;
        const int r0 = 16 * mf + gid, r1 = r0 + 8;
        const uint32_t Ap1 = sb + (isGh ? CG_AH1 : CG_AM1);
        const uint32_t Ap2 = sb + (isGh ? CG_AH2 : CG_AM2);
        const uint32_t Bb = sb + (isGh ? CG_BWHH : CG_BWIH);
        const float* bias = isGh ? bhh : bih;
        float* dst = isGh ? sgh : sgi;

        float C[12][4];
#pragma unroll
        for (int pr = 0; pr < 6; pr++)
#pragma unroll
            for (int g = 0; g < 2; g++) {
                int col = cbase + pr * 16 + g * 8 + tpair;
                float2 bv = *(const float2*)(bias + col);
                C[2 * pr + g][0] = bv.x; C[2 * pr + g][1] = bv.y;
                C[2 * pr + g][2] = bv.x; C[2 * pr + g][3] = bv.y;
            }
        const uint32_t bo = Bb +
            (uint32_t)((cbase + (lane >> 4) * 8 + (lane & 7)) * 144 +
                       ((lane >> 3) & 1) * 16);
#pragma unroll
        for (int kf = 0; kf < 4; kf++) {
            uint32_t fa1[4], fa2[4];
            LDSM4(fa1, Ap1 + aoff + kf * 32);
            LDSM4(fa2, Ap2 + aoff + kf * 32);
#pragma unroll
            for (int pr = 0; pr < 6; pr++) {
                uint32_t b1[4], b2[4];
                LDSM4(b1, bo + pr * 2304 + kf * 32);
                MMA_F16(C[2 * pr],     fa1, b1[0], b1[1]);
                MMA_F16(C[2 * pr + 1], fa1, b1[2], b1[3]);
                MMA_F16(C[2 * pr],     fa2, b1[0], b1[1]);
                MMA_F16(C[2 * pr + 1], fa2, b1[2], b1[3]);
                LDSM4(b2, bo + 27648 + pr * 2304 + kf * 32);
                MMA_F16(C[2 * pr],     fa1, b2[0], b2[1]);
                MMA_F16(C[2 * pr + 1], fa1, b2[2], b2[3]);
            }
        }
        // C -> sgi/sgh fp32
#pragma unroll
        for (int pr = 0; pr < 6; pr++)
#pragma unroll
            for (int g = 0; g < 2; g++) {
                int col = cbase + pr * 16 + g * 8 + tpair;
                *(float2*)(dst + r0 * 196 + col) =
                    make_float2(C[2 * pr + g][0], C[2 * pr + g][1]);
                *(float2*)(dst + r1 * 196 + col) =
                    make_float2(C[2 * pr + g][2], C[2 * pr + g][3]);
            }
    }
    __syncthreads();

    // ---- gates ----
    for (int i = tid; i < 2048; i += 256) {
        int n = i >> 6, c = i & 63;
        const float* gi = sgi + n * 196;
        const float* gh = sgh + n * 196;
        float r = 1.f / (1.f + expf(-(gi[c] + gh[c])));
        float z = 1.f / (1.f + expf(-(gi[64 + c] + gh[64 + c])));
        float nc = tanhf(gi[128 + c] + r * gh[128 + c]);
        float v = (1.f - z) * nc + z * shr[n * 68 + c];
        size_t o = (size_t)(n0 + n) * 64 + c;
        g_h[o] = v;
        if (outp) outp[o] = v;
        __half a, b; split16(v, a, b);
        g_h1[o] = a; g_h2[o] = b;
    }
}

// ---------------- K7: edge-update MLP, 32-edge CTAs, occ 2 -----------------
#define EU_SMEM   104960
#define EU_OFF_A  1536
#define EU_A_PL   16896
#define EU_OFF_B  35328
#define EU_T_PL   8704
#define EU_B2_PL  34816
extern "C" __global__ void __launch_bounds__(256, 2)
k_edgeup_tc(const int* __restrict__ eidx,
            const float* __restrict__ b1, const float* __restrict__ b2,
            float* __restrict__ oute) {
    extern __shared__ char sm[];
    const uint32_t sbase = smem_u32(sm);
    int* sc = (int*)sm;
    int* tcs = (int*)(sm + 128);
    float* b1s = (float*)(sm + 512);
    float* b2s = (float*)(sm + 1024);

    const int tid = threadIdx.x;
    const int e0 = blockIdx.x * 32;
    const int w = tid >> 5, lane = tid & 31;

    if (tid < 32)      sc[tid] = eidx[e0 + tid];
    else if (tid < 64) tcs[tid - 32] = eidx[N_EDGES + e0 + (tid - 32)];
    else if (tid < 192) b1s[tid - 64] = b1[tid - 64];
    else               b2s[tid - 192] = b2[tid - 192];
    if (tid < 64) b2s[64 + tid] = b2[64 + tid];

    for (int i = tid; i < 4096; i += 256) {
        int n = i >> 5, c = i & 31;
        CP_ASYNC16(sbase + EU_OFF_B + n * 528 + c * 16,
                   g_We1T1 + (size_t)n * 256 + c * 8);
    }
    CP_COMMIT();
    __syncthreads();

    for (int i = tid; i < 512; i += 256) {
        int s2 = i >> 8, j = i & 255;
        int l = j >> 3, c = (j & 7) * 8;
        int nrow = s2 ? tcs[l] : sc[l];
        const uint4* s1 = (const uint4*)(g_h1 + (size_t)nrow * 64 + c);
        const uint4* s2p = (const uint4*)(g_h2 + (size_t)nrow * 64 + c);
        char* dst = sm + EU_OFF_A + l * 528 + s2 * 128 + c * 2;
        *(uint4*)dst = *s1;
        *(uint4*)(dst + EU_A_PL) = *s2p;
    }
    for (int i = tid; i < 512; i += 256) {
        int l = i >> 4, c = (i & 15) * 8;
        const uint4* s1 = (const uint4*)(g_e1 + (size_t)(e0 + l) * 128 + c);
        const uint4* s2p = (const uint4*)(g_e2 + (size_t)(e0 + l) * 128 + c);
        char* dst = sm + EU_OFF_A + l * 528 + 256 + c * 2;
        *(uint4*)dst = *s1;
        *(uint4*)(dst + EU_A_PL) = *s2p;
    }
    CP_WAIT_ALL();
    __syncthreads();

    const int mf = w & 1, nh = w >> 1;
    const int nbase = nh * 32;
    const int gid = lane >> 2, tpair = (lane & 3) * 2;
    const uint32_t aoff = (uint32_t)((16 * mf + (lane & 15)) * 528 + (lane >> 4) * 16);
    const uint32_t boff = (uint32_t)((nbase + (lane >> 4) * 8 + (lane & 7)) * 528 +
                                     ((lane >> 3) & 1) * 16);

    float C[4][4];
#pragma unroll
    for (int nf = 0; nf < 4; nf++) {
        float2 bv = *(const float2*)(b1s + nbase + nf * 8 + tpair);
        C[nf][0] = bv.x; C[nf][1] = bv.y;
        C[nf][2] = bv.x; C[nf][3] = bv.y;
    }

#pragma unroll
    for (int kf = 0; kf < 16; kf++) {
        uint32_t fa1[4], fa2[4];
        LDSM4(fa1, sbase + EU_OFF_A + aoff + kf * 32);
        LDSM4(fa2, sbase + EU_OFF_A + EU_A_PL + aoff + kf * 32);
#pragma unroll
        for (int p = 0; p < 2; p++) {
            uint32_t b[4];
            LDSM4(b, sbase + EU_OFF_B + boff + p * 8448 + kf * 32);
            MMA_F16(C[2 * p],     fa1, b[0], b[1]);
            MMA_F16(C[2 * p],     fa2, b[0], b[1]);
            MMA_F16(C[2 * p + 1], fa1, b[2], b[3]);
            MMA_F16(C[2 * p + 1], fa2, b[2], b[3]);
        }
    }
    __syncthreads();

    for (int i = tid; i < 4096; i += 256) {
        int n = i >> 5, c = i & 31;
        CP_ASYNC16(sbase + EU_OFF_B + n * 528 + c * 16,
                   g_We1T2 + (size_t)n * 256 + c * 8);
    }
    CP_COMMIT();
    CP_WAIT_ALL();
    __syncthreads();

#pragma unroll
    for (int kf = 0; kf < 16; kf++) {
        uint32_t fa1[4];
        LDSM4(fa1, sbase + EU_OFF_A + aoff + kf * 32);
#pragma unroll
        for (int p = 0; p < 2; p++) {
            uint32_t b[4];
            LDSM4(b, sbase + EU_OFF_B + boff + p * 8448 + kf * 32);
            MMA_F16(C[2 * p],     fa1, b[0], b[1]);
            MMA_F16(C[2 * p + 1], fa1, b[2], b[3]);
        }
    }
    __syncthreads();

    for (int i = tid; i < 4096; i += 256) {
        int p = i >> 11, n = (i >> 4) & 127, c = i & 15;
        const __half* src = (p ? g_We2T2 : g_We2T1) + (size_t)n * 128 + c * 8;
        CP_ASYNC16(sbase + EU_OFF_B + p * EU_B2_PL + n * 272 + c * 16, src);
    }
    CP_COMMIT();

    {
        int r0 = 16 * mf + gid;
#pragma unroll
        for (int nf = 0; nf < 4; nf++) {
            int col = nbase + nf * 8 + tpair;
#pragma unroll
            for (int half = 0; half < 2; half++) {
                int r = r0 + half * 8;
                float v0 = fmaxf(C[nf][2 * half], 0.f);
                float v1 = fmaxf(C[nf][2 * half + 1], 0.f);
                __half a0, c0, a1_, c1;
                split16(v0, a0, c0);
                split16(v1, a1_, c1);
                char* base = sm + EU_OFF_A + r * 272 + col * 2;
                *(__half2*)base = __halves2half2(a0, a1_);
                *(__half2*)(base + EU_T_PL) = __halves2half2(c0, c1);
            }
        }
    }
    CP_WAIT_ALL();
    __syncthreads();

    const uint32_t toff = (uint32_t)((16 * mf + (lane & 15)) * 272 + (lane >> 4) * 16);
    const uint32_t b2off = (uint32_t)((nbase + (lane & 7)) * 272 +
                                      ((lane >> 3) & 1) * 16 +
                                      (lane >> 4) * EU_B2_PL);
    float C2[4][4];
#pragma unroll
    for (int nf = 0; nf < 4; nf++) {
        float2 bv = *(const float2*)(b2s + nbase + nf * 8 + tpair);
        C2[nf][0] = bv.x; C2[nf][1] = bv.y;
        C2[nf][2] = bv.x; C2[nf][3] = bv.y;
    }
#pragma unroll
    for (int kf = 0; kf < 8; kf++) {
        uint32_t fa1[4], fa2[4];
        LDSM4(fa1, sbase + EU_OFF_A + toff + kf * 32);
        LDSM4(fa2, sbase + EU_OFF_A + EU_T_PL + toff + kf * 32);
#pragma unroll
        for (int nf = 0; nf < 4; nf++) {
            uint32_t b[4];
            LDSM4(b, sbase + EU_OFF_B + b2off + nf * 2176 + kf * 32);
            MMA_F16(C2[nf], fa1, b[0], b[1]);
            MMA_F16(C2[nf], fa2, b[0], b[1]);
            MMA_F16(C2[nf], fa1, b[2], b[3]);
        }
    }

    {
        int r0 = 16 * mf + gid;
#pragma unroll
        for (int nf = 0; nf < 4; nf++) {
            int col = nbase + nf * 8 + tpair;
#pragma unroll
            for (int half = 0; half < 2; half++) {
                int r = r0 + half * 8;
                size_t o = (size_t)(e0 + r) * 128 + col;
                float v0 = fmaxf(C2[nf][2 * half], 0.f);
                float v1 = fmaxf(C2[nf][2 * half + 1], 0.f);
                g_e[o] = v0; g_e[o + 1] = v1;
                if (oute) { oute[o] = v0; oute[o + 1] = v1; }
                __half a0, c0, a1_, c1;
                split16(v0, a0, c0);
                split16(v1, a1_, c1);
                *(__half2*)(g_e1 + o) = __halves2half2(a0, a1_);
                *(__half2*)(g_e2 + o) = __halves2half2(c0, c1);
            }
        }
    }
}

// ---------------- launcher -------------------------------------------------
extern "C" void kernel_launch(void* const* d_in, const int* in_sizes, int n_in,
                              void* d_out, int out_size) {
    const float* nf   = (const float*)d_in[0];
    const float* ea   = (const float*)d_in[1];
    const int*   eidx = (const int*)  d_in[2];
    const float* Wp   = (const float*)d_in[3];
    const float* bp   = (const float*)d_in[4];
    const float* Wpe  = (const float*)d_in[5];
    const float* bpe  = (const float*)d_in[6];
    const float* Wnn  = (const float*)d_in[7];
    const float* bnn  = (const float*)d_in[8];
    const float* Wr   = (const float*)d_in[9];
    const float* bc   = (const float*)d_in[10];
    const float* wih  = (const float*)d_in[11];
    const float* whh  = (const float*)d_in[12];
    const float* bih  = (const float*)d_in[13];
    const float* bhh  = (const float*)d_in[14];
    const float* We1  = (const float*)d_in[15];
    const float* be1  = (const float*)d_in[16];
    const float* We2  = (const float*)d_in[17];
    const float* be2  = (const float*)d_in[18];

    float* out_h = (float*)d_out;
    float* out_e = (float*)d_out + (size_t)N_NODES * DIM;

    cudaFuncSetAttribute(k_nnconv_mma, cudaFuncAttributeMaxDynamicSharedMemorySize, NC_SMEM);
    cudaFuncSetAttribute(k_edgeup_tc, cudaFuncAttributeMaxDynamicSharedMemorySize, EU_SMEM);
    cudaFuncSetAttribute(k_conv_gru_tc, cudaFuncAttributeMaxDynamicSharedMemorySize, CG_SMEM);

    k_split_all<<<588, dim3(32, 8)>>>(Wnn, We1, We2, Wr, wih, whh);
    k_proj<<<1024 + N_EDGES / 2, 256>>>(nf, Wp, bp, ea, Wpe, bpe);

    for (int step = 0; step < NUM_STEPS; step++) {
        bool last = (step == NUM_STEPS - 1);
        k_nnconv_mma<<<(N_EDGES / 128) * 4, 256, NC_SMEM>>>(eidx, bnn);
        k_conv_gru_tc<<<N_NODES / 32, 256, CG_SMEM>>>(bc, bih, bhh,
                                                      last ? out_h : (float*)nullptr);
        k_edgeup_tc<<<N_EDGES / 32, 256, EU_SMEM>>>(eidx, be1, be2,
                                                    last ? out_e : (float*)nullptr);
    }
}

// round 14
// speedup vs baseline: 1.0532x; 1.0069x over previous
#include <cuda_runtime.h>
#include <cuda_fp16.h>
#include <math.h>
#include <stdint.h>

#define N_NODES 4096
#define N_EDGES 32768
#define DIM 64
#define EHID 128
#define NUM_STEPS 3

// ---------------- scratch (device globals; zero-initialized) ----------------
__device__ float g_h[N_NODES * DIM];
__device__ float g_e[N_EDGES * EHID];
__device__ float g_agg[N_NODES * DIM];    // invariant: zero at kernel_launch entry
__device__ __half g_h1[N_NODES * DIM];
__device__ __half g_h2[N_NODES * DIM];
__device__ __half g_e1[N_EDGES * EHID];
__device__ __half g_e2[N_EDGES * EHID];
__device__ __half g_Wt1[4096 * 128];      // W_nn^T [n][k] limb1
__device__ __half g_We1T1[128 * 256];
__device__ __half g_We1T2[128 * 256];
__device__ __half g_We2T1[128 * 128];
__device__ __half g_We2T2[128 * 128];
__device__ __half g_WrT1[64 * 64],   g_WrT2[64 * 64];
__device__ __half g_WihT1[192 * 64], g_WihT2[192 * 64];
__device__ __half g_WhhT1[192 * 64], g_WhhT2[192 * 64];

// ---------------- helpers ---------------------------------------------------
__device__ __forceinline__ uint32_t smem_u32(const void* p) {
    uint32_t a;
    asm("{ .reg .u64 t; cvta.to.shared.u64 t, %1; cvt.u32.u64 %0, t; }"
        : "=r"(a) : "l"(p));
    return a;
}
#define LDSM4(r, addr) \
    asm volatile("ldmatrix.sync.aligned.m8n8.x4.shared.b16 {%0,%1,%2,%3}, [%4];" \
        : "=r"((r)[0]), "=r"((r)[1]), "=r"((r)[2]), "=r"((r)[3]) : "r"(addr))
#define MMA_F16(C, A, b0, b1) \
    asm volatile("mma.sync.aligned.m16n8k16.row.col.f32.f16.f16.f32 " \
        "{%0,%1,%2,%3},{%4,%5,%6,%7},{%8,%9},{%0,%1,%2,%3};" \
        : "+f"((C)[0]), "+f"((C)[1]), "+f"((C)[2]), "+f"((C)[3]) \
        : "r"((A)[0]), "r"((A)[1]), "r"((A)[2]), "r"((A)[3]), "r"(b0), "r"(b1))
#define CP_ASYNC16(dst, src) \
    asm volatile("cp.async.ca.shared.global [%0], [%1], 16;" :: "r"(dst), "l"(src))
#define CP_COMMIT() asm volatile("cp.async.commit_group;")
#define CP_WAIT_ALL() asm volatile("cp.async.wait_all;")
#define CP_WAIT_GROUP(n) asm volatile("cp.async.wait_group %0;" :: "n"(n))

__device__ __forceinline__ void split16(float v, __half& a, __half& b) {
    a = __float2half(v);
    b = __float2half(v - __half2float(a));
}

// ---------------- K0: fused setup (weight splits + projections) ------------
// blocks [0,588): transpose + limb-split of 6 weight mats
// blocks [588, 588+1024): node projection; rest: edge projection
__global__ void k_setup(const float* __restrict__ Wnn,
                        const float* __restrict__ We1,
                        const float* __restrict__ We2,
                        const float* __restrict__ Wr,
                        const float* __restrict__ wih,
                        const float* __restrict__ whh,
                        const float* __restrict__ nf,
                        const float* __restrict__ Wp,
                        const float* __restrict__ bp,
                        const float* __restrict__ ea,
                        const float* __restrict__ Wpe,
                        const float* __restrict__ bpe) {
    __shared__ float shm[1056];
    int tid = threadIdx.x;
    int blk = blockIdx.x;
    if (blk < 588) {
        float (*t)[33] = (float (*)[33])shm;
        int x = tid & 31, y = tid >> 5;               // 32 x 8
        int b = blk;
        const float* W; int K, N, sel, bx, by;
        if (b < 512)      { W = Wnn; K = 128; N = 4096; sel = 0; bx = b & 127; by = b >> 7; }
        else if (b < 544) { b -= 512; W = We1; K = 256; N = 128; sel = 1; bx = b & 3; by = b >> 2; }
        else if (b < 560) { b -= 544; W = We2; K = 128; N = 128; sel = 2; bx = b & 3; by = b >> 2; }
        else if (b < 564) { b -= 560; W = Wr;  K = 64;  N = 64;  sel = 3; bx = b & 1; by = b >> 1; }
        else if (b < 576) { b -= 564; W = wih; K = 64;  N = 192; sel = 4; bx = b % 6; by = b / 6; }
        else              { b -= 576; W = whh; K = 64;  N = 192; sel = 5; bx = b % 6; by = b / 6; }
        int nb = bx * 32, kb = by * 32;
#pragma unroll
        for (int i = 0; i < 4; i++)
            t[y + 8 * i][x] = W[(size_t)(kb + y + 8 * i) * N + nb + x];
        __syncthreads();
        __half *d1, *d2 = nullptr;
        switch (sel) {
            case 0: d1 = g_Wt1; break;
            case 1: d1 = g_We1T1; d2 = g_We1T2; break;
            case 2: d1 = g_We2T1; d2 = g_We2T2; break;
            case 3: d1 = g_WrT1;  d2 = g_WrT2;  break;
            case 4: d1 = g_WihT1; d2 = g_WihT2; break;
            default: d1 = g_WhhT1; d2 = g_WhhT2; break;
        }
#pragma unroll
        for (int i = 0; i < 4; i++) {
            float v = t[x][y + 8 * i];
            size_t o = (size_t)(nb + y + 8 * i) * K + kb + x;
            __half a, b2; split16(v, a, b2);
            d1[o] = a;
            if (d2) d2[o] = b2;
        }
    } else if (blk < 588 + 1024) {
        float* s = shm;
        int n0 = (blk - 588) * 4;
        s[tid] = nf[(size_t)n0 * 64 + tid];
        __syncthreads();
        int nl = tid >> 6, c = tid & 63;
        float sum = bp[c];
#pragma unroll 16
        for (int k = 0; k < 64; k++) sum += s[nl * 64 + k] * Wp[k * 64 + c];
        float v = fmaxf(sum, 0.f);
        size_t o = (size_t)(n0 + nl) * 64 + c;
        g_h[o] = v;
        __half a, b; split16(v, a, b);
        g_h1[o] = a; g_h2[o] = b;
    } else {
        float* s = shm;
        int e0 = (blk - 588 - 1024) * 2;
        if (tid < 32) s[tid] = ea[(size_t)e0 * 16 + tid];
        __syncthreads();
        int el = tid >> 7, c = tid & 127;
        float sum = bpe[c];
#pragma unroll
        for (int k = 0; k < 16; k++) sum += s[el * 16 + k] * Wpe[k * 128 + c];
        float v = fmaxf(sum, 0.f);
        size_t idx = (size_t)(e0 + el) * 128 + c;
        g_e[idx] = v;
        __half a, b; split16(v, a, b);
        g_e1[idx] = a; g_e2[idx] = b;
    }
}

// ---------------- K4: NNConv, fp16 single-pass mma, n-split x4 -------------
#define NC_SMEM 55808
#define OFF_BIAS 1024
#define OFF_HS   5120
#define OFF_AB   38400
extern "C" __global__ void __launch_bounds__(256, 3)
k_nnconv_mma(const int* __restrict__ eidx, const float* __restrict__ b_nn) {
    extern __shared__ char sm[];
    int* sc = (int*)sm;
    int* tcs = (int*)(sm + 512);
    float* sbias = (float*)(sm + OFF_BIAS);
    float* hs = (float*)(sm + OFF_HS);
    char* AB = sm + OFF_AB;
    const uint32_t ABu = smem_u32(AB);

    const int tid = threadIdx.x;
    const int q = blockIdx.x & 3;
    const int e0 = (blockIdx.x >> 2) * 128;
    const int ncol0 = q * 16;
    const int w = tid >> 5, lane = tid & 31;

    if (tid < 128) sc[tid] = eidx[e0 + tid];
    else           tcs[tid - 128] = eidx[N_EDGES + e0 + (tid - 128)];
    {
        int d = tid >> 2, jq = tid & 3;
        *(float4*)(sbias + d * 16 + jq * 4) =
            *(const float4*)(b_nn + d * 64 + ncol0 + jq * 4);
    }
    __syncthreads();

    {
        int l = tid >> 1, d0 = (tid & 1) * 32;
        const float* hrow = g_h + (size_t)sc[l] * 64 + d0;
        float* dst = hs + l * 65 + d0;
#pragma unroll
        for (int i = 0; i < 32; i += 4) {
            float4 v = *(const float4*)(hrow + i);
            dst[i] = v.x; dst[i + 1] = v.y; dst[i + 2] = v.z; dst[i + 3] = v.w;
        }
    }

    uint32_t a1[8][4];
    {
        const uint4* s1 = (const uint4*)(g_e1 + (size_t)e0 * 128);
#pragma unroll
        for (int r = 0; r < 2; r++) {
            __syncthreads();
#pragma unroll
            for (int it = 0; it < 4; it++) {
                int idx = it * 256 + tid;
                int row = idx >> 4, sl = idx & 15;
                *(uint4*)(AB + row * 272 + sl * 16) = s1[(64 * r + row) * 16 + sl];
            }
            __syncthreads();
            if ((w >> 2) == r) {
                uint32_t base = ABu + (uint32_t)((16 * (w & 3) + (lane & 15)) * 272 +
                                                 (lane >> 4) * 16);
#pragma unroll
                for (int kf = 0; kf < 8; kf++) LDSM4(a1[kf], base + kf * 32);
            }
        }
        __syncthreads();
    }

    {
        int row = tid >> 4, sl = tid & 15;
        CP_ASYNC16(ABu + row * 272 + sl * 16,
                   g_Wt1 + (size_t)(ncol0 + row) * 128 + sl * 8);
    }
    CP_COMMIT();

    const int gid = lane >> 2, tpair = (lane & 3) * 2;
    const int row0 = 16 * w + gid;
    const float* hvp0 = hs + row0 * 65;
    const float* hvp1 = hs + (row0 + 8) * 65;
    const uint32_t boff = (uint32_t)((lane & 7) * 272 + ((lane >> 3) & 1) * 16 +
                                     (lane >> 4) * 2176);
    float msg[2][4] = {};

    for (int d = 0; d < 64; d++) {
        CP_WAIT_ALL();
        __syncthreads();
        if (d + 1 < 64) {
            int row = tid >> 4, sl = tid & 15;
            CP_ASYNC16(ABu + ((d + 1) & 1) * 4352 + row * 272 + sl * 16,
                       g_Wt1 + (size_t)((d + 1) * 64 + ncol0 + row) * 128 + sl * 8);
            CP_COMMIT();
        }

        float C[2][4];
        const float* bptr = sbias + d * 16 + tpair;
#pragma unroll
        for (int nf = 0; nf < 2; nf++) {
            float2 bv = *(const float2*)(bptr + nf * 8);
            C[nf][0] = bv.x; C[nf][1] = bv.y;
            C[nf][2] = bv.x; C[nf][3] = bv.y;
        }
        const uint32_t bb = ABu + (d & 1) * 4352 + boff;
#pragma unroll
        for (int kf = 0; kf < 8; kf++) {
            uint32_t b[4];
            LDSM4(b, bb + kf * 32);
            MMA_F16(C[0], a1[kf], b[0], b[1]);
            MMA_F16(C[1], a1[kf], b[2], b[3]);
        }
        float hv0 = hvp0[d], hv1 = hvp1[d];
#pragma unroll
        for (int nf = 0; nf < 2; nf++) {
            msg[nf][0] = fmaf(hv0, fmaxf(C[nf][0], 0.f), msg[nf][0]);
            msg[nf][1] = fmaf(hv0, fmaxf(C[nf][1], 0.f), msg[nf][1]);
            msg[nf][2] = fmaf(hv1, fmaxf(C[nf][2], 0.f), msg[nf][2]);
            msg[nf][3] = fmaf(hv1, fmaxf(C[nf][3], 0.f), msg[nf][3]);
        }
    }

    float* d0 = g_agg + (size_t)tcs[row0] * 64 + ncol0 + tpair;
    float* d1 = g_agg + (size_t)tcs[row0 + 8] * 64 + ncol0 + tpair;
#pragma unroll
    for (int nf = 0; nf < 2; nf++) {
        atomicAdd(d0 + nf * 8,     msg[nf][0]);
        atomicAdd(d0 + nf * 8 + 1, msg[nf][1]);
        atomicAdd(d1 + nf * 8,     msg[nf][2]);
        atomicAdd(d1 + nf * 8 + 1, msg[nf][3]);
    }
}

// ---------------- K5+K6: conv + GRU on tensor cores, 512 threads -----------
// 16 warps. group0 cp.async: Wr + h-limbs + whh; group1: wih.
// Warps 0-7: phase1 (m = relu(agg + h@Wr + bc)); warps 8-15 CONCURRENT:
// gh = h@whh + bhh. Then warps 0-11: gi = m@wih + bih. Gates 512 thr.
// Per-C-frag order: bias seed; kf asc; fa1*b1, fa2*b1, fa1*b2 (== R13).
#define CG_SMEM  206336
#define CG_SHR   0
#define CG_AH1   8704
#define CG_AH2   13312
#define CG_AM1   17920
#define CG_AM2   22528
#define CG_BWR   27136
#define CG_BWIH  45568
#define CG_BWHH  100864
#define CG_SGI   156160
#define CG_SGH   181248
__global__ void __launch_bounds__(512, 1)
k_conv_gru_tc(const float* __restrict__ bc,
              const float* __restrict__ bih, const float* __restrict__ bhh,
              float* __restrict__ outp) {
    extern __shared__ char sm[];
    const uint32_t sb = smem_u32(sm);
    float* shr = (float*)(sm + CG_SHR);
    float* sgi = (float*)(sm + CG_SGI);
    float* sgh = (float*)(sm + CG_SGH);

    const int tid = threadIdx.x;
    const int n0 = blockIdx.x * 32;
    const int w = tid >> 5, lane = tid & 31;
    const int gid = lane >> 2, tpair = (lane & 3) * 2;

    // ---- group 0: Wr + h limbs + whh ----
    for (int i = tid; i < 1024; i += 512) {           // Wr
        int pl = i >> 9, n = (i >> 3) & 63, c = i & 7;
        CP_ASYNC16(sb + CG_BWR + pl * 9216 + n * 144 + c * 16,
                   (pl ? g_WrT2 : g_WrT1) + (size_t)n * 64 + c * 8);
    }
    for (int i = tid; i < 512; i += 512) {            // h limbs
        int pl = i >> 8, n = (i >> 3) & 31, c = i & 7;
        CP_ASYNC16(sb + (pl ? CG_AH2 : CG_AH1) + n * 144 + c * 16,
                   (pl ? g_h2 : g_h1) + (size_t)(n0 + n) * 64 + c * 8);
    }
    for (int i = tid; i < 3072; i += 512) {           // whh: 192r x 8c x 2pl
        int pl = i / 1536, r = i % 1536;
        int n = r >> 3, c = r & 7;
        CP_ASYNC16(sb + CG_BWHH + pl * 27648 + n * 144 + c * 16,
                   (pl ? g_WhhT2 : g_WhhT1) + (size_t)n * 64 + c * 8);
    }
    CP_COMMIT();
    // ---- group 1: wih ----
    for (int i = tid; i < 3072; i += 512) {
        int pl = i / 1536, r = i % 1536;
        int n = r >> 3, c = r & 7;
        CP_ASYNC16(sb + CG_BWIH + pl * 27648 + n * 144 + c * 16,
                   (pl ? g_WihT2 : g_WihT1) + (size_t)n * 64 + c * 8);
    }
    CP_COMMIT();
    // shr fp32
    if (tid < 256) {
        int n = tid >> 3, c8 = (tid & 7) * 8;
        float4 va = *(const float4*)(g_h + (size_t)(n0 + n) * 64 + c8);
        float4 vb = *(const float4*)(g_h + (size_t)(n0 + n) * 64 + c8 + 4);
        float* dst = shr + n * 68 + c8;
        *(float4*)dst = va;
        *(float4*)(dst + 4) = vb;
    }
    CP_WAIT_GROUP(1);   // group 0 complete
    __syncthreads();

    const uint32_t aoff = (uint32_t)((16 * (w & 1) + (lane & 15)) * 144 +
                                     (lane >> 4) * 16);

    if (w < 8) {
        // ---- phase 1: conv; warp = (mf = w&1, nh = w>>1) -> cols nh*16..+15
        const int mf = w & 1, nh = w >> 1;
        const int r0 = 16 * mf + gid, r1 = r0 + 8;
        float C[2][4];
#pragma unroll
        for (int g = 0; g < 2; g++) {
            int col = nh * 16 + g * 8 + tpair;
            float2 bv = *(const float2*)(bc + col);
            float* a0p = g_agg + (size_t)(n0 + r0) * 64 + col;
            float* a1p = g_agg + (size_t)(n0 + r1) * 64 + col;
            float2 a0 = *(float2*)a0p;
            float2 a1v = *(float2*)a1p;
            *(float2*)a0p = make_float2(0.f, 0.f);
            *(float2*)a1p = make_float2(0.f, 0.f);
            C[g][0] = bv.x + a0.x;  C[g][1] = bv.y + a0.y;
            C[g][2] = bv.x + a1v.x; C[g][3] = bv.y + a1v.y;
        }
        const uint32_t bo = sb + CG_BWR +
            (uint32_t)((nh * 16 + (lane >> 4) * 8 + (lane & 7)) * 144 +
                       ((lane >> 3) & 1) * 16);
#pragma unroll
        for (int kf = 0; kf < 4; kf++) {
            uint32_t fa1[4], fa2[4], b1[4], b2[4];
            LDSM4(fa1, sb + CG_AH1 + aoff + kf * 32);
            LDSM4(fa2, sb + CG_AH2 + aoff + kf * 32);
            LDSM4(b1, bo + kf * 32);
            MMA_F16(C[0], fa1, b1[0], b1[1]);
            MMA_F16(C[1], fa1, b1[2], b1[3]);
            MMA_F16(C[0], fa2, b1[0], b1[1]);
            MMA_F16(C[1], fa2, b1[2], b1[3]);
            LDSM4(b2, bo + 9216 + kf * 32);
            MMA_F16(C[0], fa1, b2[0], b2[1]);
            MMA_F16(C[1], fa1, b2[2], b2[3]);
        }
#pragma unroll
        for (int g = 0; g < 2; g++) {
            int col = nh * 16 + g * 8 + tpair;
#pragma unroll
            for (int half = 0; half < 2; half++) {
                int r = (half ? r1 : r0);
                float v0 = fmaxf(C[g][2 * half], 0.f);
                float v1 = fmaxf(C[g][2 * half + 1], 0.f);
                __half a0, c0, a1h, c1;
                split16(v0, a0, c0);
                split16(v1, a1h, c1);
                *(__half2*)(sm + CG_AM1 + r * 144 + col * 2) = __halves2half2(a0, a1h);
                *(__half2*)(sm + CG_AM2 + r * 144 + col * 2) = __halves2half2(c0, c1);
            }
        }
    } else {
        // ---- CONCURRENT gh = h@whh + bhh; warp = (mf, cgh = (w-8)>>1) ----
        const int mf = w & 1, cgh = (w - 8) >> 1;
        const int cbase = cgh * 48;
        const int r0 = 16 * mf + gid, r1 = r0 + 8;
        float C[6][4];
#pragma unroll
        for (int pr = 0; pr < 3; pr++)
#pragma unroll
            for (int g = 0; g < 2; g++) {
                int col = cbase + pr * 16 + g * 8 + tpair;
                float2 bv = *(const float2*)(bhh + col);
                C[2 * pr + g][0] = bv.x; C[2 * pr + g][1] = bv.y;
                C[2 * pr + g][2] = bv.x; C[2 * pr + g][3] = bv.y;
            }
        const uint32_t bo = sb + CG_BWHH +
            (uint32_t)((cbase + (lane >> 4) * 8 + (lane & 7)) * 144 +
                       ((lane >> 3) & 1) * 16);
#pragma unroll
        for (int kf = 0; kf < 4; kf++) {
            uint32_t fa1[4], fa2[4];
            LDSM4(fa1, sb + CG_AH1 + aoff + kf * 32);
            LDSM4(fa2, sb + CG_AH2 + aoff + kf * 32);
#pragma unroll
            for (int pr = 0; pr < 3; pr++) {
                uint32_t b1[4], b2[4];
                LDSM4(b1, bo + pr * 2304 + kf * 32);
                MMA_F16(C[2 * pr],     fa1, b1[0], b1[1]);
                MMA_F16(C[2 * pr + 1], fa1, b1[2], b1[3]);
                MMA_F16(C[2 * pr],     fa2, b1[0], b1[1]);
                MMA_F16(C[2 * pr + 1], fa2, b1[2], b1[3]);
                LDSM4(b2, bo + 27648 + pr * 2304 + kf * 32);
                MMA_F16(C[2 * pr],     fa1, b2[0], b2[1]);
                MMA_F16(C[2 * pr + 1], fa1, b2[2], b2[3]);
            }
        }
#pragma unroll
        for (int pr = 0; pr < 3; pr++)
#pragma unroll
            for (int g = 0; g < 2; g++) {
                int col = cbase + pr * 16 + g * 8 + tpair;
                *(float2*)(sgh + r0 * 196 + col) =
                    make_float2(C[2 * pr + g][0], C[2 * pr + g][1]);
                *(float2*)(sgh + r1 * 196 + col) =
                    make_float2(C[2 * pr + g][2], C[2 * pr + g][3]);
            }
    }
    CP_WAIT_GROUP(0);
    __syncthreads();

    // ---- gi = m@wih + bih; warps 0-11: (mf = w&1, cgi = w>>1) -> 32 cols ----
    if (w < 12) {
        const int mf = w & 1, cgi = w >> 1;
        const int cbase = cgi * 32;
        const int r0 = 16 * mf + gid, r1 = r0 + 8;
        float C[4][4];
#pragma unroll
        for (int pr = 0; pr < 2; pr++)
#pragma unroll
            for (int g = 0; g < 2; g++) {
                int col = cbase + pr * 16 + g * 8 + tpair;
                float2 bv = *(const float2*)(bih + col);
                C[2 * pr + g][0] = bv.x; C[2 * pr + g][1] = bv.y;
                C[2 * pr + g][2] = bv.x; C[2 * pr + g][3] = bv.y;
            }
        const uint32_t bo = sb + CG_BWIH +
            (uint32_t)((cbase + (lane >> 4) * 8 + (lane & 7)) * 144 +
                       ((lane >> 3) & 1) * 16);
#pragma unroll
        for (int kf = 0; kf < 4; kf++) {
            uint32_t fa1[4], fa2[4];
            LDSM4(fa1, sb + CG_AM1 + aoff + kf * 32);
            LDSM4(fa2, sb + CG_AM2 + aoff + kf * 32);
#pragma unroll
            for (int pr = 0; pr < 2; pr++) {
                uint32_t b1[4], b2[4];
                LDSM4(b1, bo + pr * 2304 + kf * 32);
                MMA_F16(C[2 * pr],     fa1, b1[0], b1[1]);
                MMA_F16(C[2 * pr + 1], fa1, b1[2], b1[3]);
                MMA_F16(C[2 * pr],     fa2, b1[0], b1[1]);
                MMA_F16(C[2 * pr + 1], fa2, b1[2], b1[3]);
                LDSM4(b2, bo + 27648 + pr * 2304 + kf * 32);
                MMA_F16(C[2 * pr],     fa1, b2[0], b2[1]);
                MMA_F16(C[2 * pr + 1], fa1, b2[2], b2[3]);
            }
        }
#pragma unroll
        for (int pr = 0; pr < 2; pr++)
#pragma unroll
            for (int g = 0; g < 2; g++) {
                int col = cbase + pr * 16 + g * 8 + tpair;
                *(float2*)(sgi + r0 * 196 + col) =
                    make_float2(C[2 * pr + g][0], C[2 * pr + g][1]);
                *(float2*)(sgi + r1 * 196 + col) =
                    make_float2(C[2 * pr + g][2], C[2 * pr + g][3]);
            }
    }
    __syncthreads();

    // ---- gates ----
    for (int i = tid; i < 2048; i += 512) {
        int n = i >> 6, c = i & 63;
        const float* gi = sgi + n * 196;
        const float* gh = sgh + n * 196;
        float r = 1.f / (1.f + expf(-(gi[c] + gh[c])));
        float z = 1.f / (1.f + expf(-(gi[64 + c] + gh[64 + c])));
        float nc = tanhf(gi[128 + c] + r * gh[128 + c]);
        float v = (1.f - z) * nc + z * shr[n * 68 + c];
        size_t o = (size_t)(n0 + n) * 64 + c;
        g_h[o] = v;
        if (outp) outp[o] = v;
        __half a, b; split16(v, a, b);
        g_h1[o] = a; g_h2[o] = b;
    }
}

// ---------------- K7: edge-update MLP, 32-edge CTAs, occ 2 -----------------
#define EU_SMEM   104960
#define EU_OFF_A  1536
#define EU_A_PL   16896
#define EU_OFF_B  35328
#define EU_T_PL   8704
#define EU_B2_PL  34816
extern "C" __global__ void __launch_bounds__(256, 2)
k_edgeup_tc(const int* __restrict__ eidx,
            const float* __restrict__ b1, const float* __restrict__ b2,
            float* __restrict__ oute) {
    extern __shared__ char sm[];
    const uint32_t sbase = smem_u32(sm);
    int* sc = (int*)sm;
    int* tcs = (int*)(sm + 128);
    float* b1s = (float*)(sm + 512);
    float* b2s = (float*)(sm + 1024);

    const int tid = threadIdx.x;
    const int e0 = blockIdx.x * 32;
    const int w = tid >> 5, lane = tid & 31;

    if (tid < 32)      sc[tid] = eidx[e0 + tid];
    else if (tid < 64) tcs[tid - 32] = eidx[N_EDGES + e0 + (tid - 32)];
    else if (tid < 192) b1s[tid - 64] = b1[tid - 64];
    else               b2s[tid - 192] = b2[tid - 192];
    if (tid < 64) b2s[64 + tid] = b2[64 + tid];

    for (int i = tid; i < 4096; i += 256) {
        int n = i >> 5, c = i & 31;
        CP_ASYNC16(sbase + EU_OFF_B + n * 528 + c * 16,
                   g_We1T1 + (size_t)n * 256 + c * 8);
    }
    CP_COMMIT();
    __syncthreads();

    for (int i = tid; i < 512; i += 256) {
        int s2 = i >> 8, j = i & 255;
        int l = j >> 3, c = (j & 7) * 8;
        int nrow = s2 ? tcs[l] : sc[l];
        const uint4* s1 = (const uint4*)(g_h1 + (size_t)nrow * 64 + c);
        const uint4* s2p = (const uint4*)(g_h2 + (size_t)nrow * 64 + c);
        char* dst = sm + EU_OFF_A + l * 528 + s2 * 128 + c * 2;
        *(uint4*)dst = *s1;
        *(uint4*)(dst + EU_A_PL) = *s2p;
    }
    for (int i = tid; i < 512; i += 256) {
        int l = i >> 4, c = (i & 15) * 8;
        const uint4* s1 = (const uint4*)(g_e1 + (size_t)(e0 + l) * 128 + c);
        const uint4* s2p = (const uint4*)(g_e2 + (size_t)(e0 + l) * 128 + c);
        char* dst = sm + EU_OFF_A + l * 528 + 256 + c * 2;
        *(uint4*)dst = *s1;
        *(uint4*)(dst + EU_A_PL) = *s2p;
    }
    CP_WAIT_ALL();
    __syncthreads();

    const int mf = w & 1, nh = w >> 1;
    const int nbase = nh * 32;
    const int gid = lane >> 2, tpair = (lane & 3) * 2;
    const uint32_t aoff = (uint32_t)((16 * mf + (lane & 15)) * 528 + (lane >> 4) * 16);
    const uint32_t boff = (uint32_t)((nbase + (lane >> 4) * 8 + (lane & 7)) * 528 +
                                     ((lane >> 3) & 1) * 16);

    float C[4][4];
#pragma unroll
    for (int nf = 0; nf < 4; nf++) {
        float2 bv = *(const float2*)(b1s + nbase + nf * 8 + tpair);
        C[nf][0] = bv.x; C[nf][1] = bv.y;
        C[nf][2] = bv.x; C[nf][3] = bv.y;
    }

#pragma unroll
    for (int kf = 0; kf < 16; kf++) {
        uint32_t fa1[4], fa2[4];
        LDSM4(fa1, sbase + EU_OFF_A + aoff + kf * 32);
        LDSM4(fa2, sbase + EU_OFF_A + EU_A_PL + aoff + kf * 32);
#pragma unroll
        for (int p = 0; p < 2; p++) {
            uint32_t b[4];
            LDSM4(b, sbase + EU_OFF_B + boff + p * 8448 + kf * 32);
            MMA_F16(C[2 * p],     fa1, b[0], b[1]);
            MMA_F16(C[2 * p],     fa2, b[0], b[1]);
            MMA_F16(C[2 * p + 1], fa1, b[2], b[3]);
            MMA_F16(C[2 * p + 1], fa2, b[2], b[3]);
        }
    }
    __syncthreads();

    for (int i = tid; i < 4096; i += 256) {
        int n = i >> 5, c = i & 31;
        CP_ASYNC16(sbase + EU_OFF_B + n * 528 + c * 16,
                   g_We1T2 + (size_t)n * 256 + c * 8);
    }
    CP_COMMIT();
    CP_WAIT_ALL();
    __syncthreads();

#pragma unroll
    for (int kf = 0; kf < 16; kf++) {
        uint32_t fa1[4];
        LDSM4(fa1, sbase + EU_OFF_A + aoff + kf * 32);
#pragma unroll
        for (int p = 0; p < 2; p++) {
            uint32_t b[4];
            LDSM4(b, sbase + EU_OFF_B + boff + p * 8448 + kf * 32);
            MMA_F16(C[2 * p],     fa1, b[0], b[1]);
            MMA_F16(C[2 * p + 1], fa1, b[2], b[3]);
        }
    }
    __syncthreads();

    for (int i = tid; i < 4096; i += 256) {
        int p = i >> 11, n = (i >> 4) & 127, c = i & 15;
        const __half* src = (p ? g_We2T2 : g_We2T1) + (size_t)n * 128 + c * 8;
        CP_ASYNC16(sbase + EU_OFF_B + p * EU_B2_PL + n * 272 + c * 16, src);
    }
    CP_COMMIT();

    {
        int r0 = 16 * mf + gid;
#pragma unroll
        for (int nf = 0; nf < 4; nf++) {
            int col = nbase + nf * 8 + tpair;
#pragma unroll
            for (int half = 0; half < 2; half++) {
                int r = r0 + half * 8;
                float v0 = fmaxf(C[nf][2 * half], 0.f);
                float v1 = fmaxf(C[nf][2 * half + 1], 0.f);
                __half a0, c0, a1_, c1;
                split16(v0, a0, c0);
                split16(v1, a1_, c1);
                char* base = sm + EU_OFF_A + r * 272 + col * 2;
                *(__half2*)base = __halves2half2(a0, a1_);
                *(__half2*)(base + EU_T_PL) = __halves2half2(c0, c1);
            }
        }
    }
    CP_WAIT_ALL();
    __syncthreads();

    const uint32_t toff = (uint32_t)((16 * mf + (lane & 15)) * 272 + (lane >> 4) * 16);
    const uint32_t b2off = (uint32_t)((nbase + (lane & 7)) * 272 +
                                      ((lane >> 3) & 1) * 16 +
                                      (lane >> 4) * EU_B2_PL);
    float C2[4][4];
#pragma unroll
    for (int nf = 0; nf < 4; nf++) {
        float2 bv = *(const float2*)(b2s + nbase + nf * 8 + tpair);
        C2[nf][0] = bv.x; C2[nf][1] = bv.y;
        C2[nf][2] = bv.x; C2[nf][3] = bv.y;
    }
#pragma unroll
    for (int kf = 0; kf < 8; kf++) {
        uint32_t fa1[4], fa2[4];
        LDSM4(fa1, sbase + EU_OFF_A + toff + kf * 32);
        LDSM4(fa2, sbase + EU_OFF_A + EU_T_PL + toff + kf * 32);
#pragma unroll
        for (int nf = 0; nf < 4; nf++) {
            uint32_t b[4];
            LDSM4(b, sbase + EU_OFF_B + b2off + nf * 2176 + kf * 32);
            MMA_F16(C2[nf], fa1, b[0], b[1]);
            MMA_F16(C2[nf], fa2, b[0], b[1]);
            MMA_F16(C2[nf], fa1, b[2], b[3]);
        }
    }

    {
        int r0 = 16 * mf + gid;
#pragma unroll
        for (int nf = 0; nf < 4; nf++) {
            int col = nbase + nf * 8 + tpair;
#pragma unroll
            for (int half = 0; half < 2; half++) {
                int r = r0 + half * 8;
                size_t o = (size_t)(e0 + r) * 128 + col;
                float v0 = fmaxf(C2[nf][2 * half], 0.f);
                float v1 = fmaxf(C2[nf][2 * half + 1], 0.f);
                g_e[o] = v0; g_e[o + 1] = v1;
                if (oute) { oute[o] = v0; oute[o + 1] = v1; }
                __half a0, c0, a1_, c1;
                split16(v0, a0, c0);
                split16(v1, a1_, c1);
                *(__half2*)(g_e1 + o) = __halves2half2(a0, a1_);
                *(__half2*)(g_e2 + o) = __halves2half2(c0, c1);
            }
        }
    }
}

// ---------------- launcher -------------------------------------------------
extern "C" void kernel_launch(void* const* d_in, const int* in_sizes, int n_in,
                              void* d_out, int out_size) {
    const float* nf   = (const float*)d_in[0];
    const float* ea   = (const float*)d_in[1];
    const int*   eidx = (const int*)  d_in[2];
    const float* Wp   = (const float*)d_in[3];
    const float* bp   = (const float*)d_in[4];
    const float* Wpe  = (const float*)d_in[5];
    const float* bpe  = (const float*)d_in[6];
    const float* Wnn  = (const float*)d_in[7];
    const float* bnn  = (const float*)d_in[8];
    const float* Wr   = (const float*)d_in[9];
    const float* bc   = (const float*)d_in[10];
    const float* wih  = (const float*)d_in[11];
    const float* whh  = (const float*)d_in[12];
    const float* bih  = (const float*)d_in[13];
    const float* bhh  = (const float*)d_in[14];
    const float* We1  = (const float*)d_in[15];
    const float* be1  = (const float*)d_in[16];
    const float* We2  = (const float*)d_in[17];
    const float* be2  = (const float*)d_in[18];

    float* out_h = (float*)d_out;
    float* out_e = (float*)d_out + (size_t)N_NODES * DIM;

    cudaFuncSetAttribute(k_nnconv_mma, cudaFuncAttributeMaxDynamicSharedMemorySize, NC_SMEM);
    cudaFuncSetAttribute(k_edgeup_tc, cudaFuncAttributeMaxDynamicSharedMemorySize, EU_SMEM);
    cudaFuncSetAttribute(k_conv_gru_tc, cudaFuncAttributeMaxDynamicSharedMemorySize, CG_SMEM);

    k_setup<<<588 + 1024 + N_EDGES / 2, 256>>>(Wnn, We1, We2, Wr, wih, whh,
                                               nf, Wp, bp, ea, Wpe, bpe);

    for (int step = 0; step < NUM_STEPS; step++) {
        bool last = (step == NUM_STEPS - 1);
        k_nnconv_mma<<<(N_EDGES / 128) * 4, 256, NC_SMEM>>>(eidx, bnn);
        k_conv_gru_tc<<<N_NODES / 32, 512, CG_SMEM>>>(bc, bih, bhh,
                                                      last ? out_h : (float*)nullptr);
        k_edgeup_tc<<<N_EDGES / 32, 256, EU_SMEM>>>(eidx, be1, be2,
                                                    last ? out_e : (float*)nullptr);
    }
}